// round 1
// baseline (speedup 1.0000x reference)
#include <cuda_runtime.h>
#include <cstdint>
#include <cstddef>

// Problem constants (fixed by the reference setup)
#define BB   8
#define TT   448
#define DD   1024
#define HH   16
#define DHH  64
#define BT   (BB * TT)              // 3584
#define QK_SCALE 0.35355339059327373f   // 64^(-0.25)

// Scratch (allocation-free rule: __device__ globals)
__device__ float g_q[(size_t)BT * DD];
__device__ float g_attn[(size_t)BT * DD];
__device__ float g_kfall[(size_t)BT * DD];
__device__ float g_vfall[(size_t)BT * DD];

// ---------------------------------------------------------------------------
// SGEMM: C[M,N] = (A[M,K] @ W[K,N] + bias[N]) * outScale
// 128x128 block tile, BK=16, 256 threads, 8x8 per thread.
// Requires M%128==0, N%128==0, K%16==0 (true for all 4 GEMMs here).
// ---------------------------------------------------------------------------
__global__ __launch_bounds__(256)
void sgemm_bias_kernel(const float* __restrict__ A, const float* __restrict__ W,
                       const float* __restrict__ bias, float* __restrict__ C,
                       int M, int N, int K, float outScale)
{
    __shared__ float As[16][128];   // A tile, transposed: As[k][m]
    __shared__ float Ws[16][128];   // W tile: Ws[k][n]

    const int tid = threadIdx.x;
    const int bm  = blockIdx.y * 128;
    const int bn  = blockIdx.x * 128;
    const int ty  = tid >> 4;
    const int tx  = tid & 15;
    const int arow = tid >> 2;            // 0..63 (two passes: +0, +64)
    const int ak   = (tid & 3) << 2;      // 0,4,8,12
    const int wrow = tid >> 5;            // 0..7  (two passes: +0, +8)
    const int wcol = (tid & 31) << 2;     // 0..124

    float acc[8][8];
#pragma unroll
    for (int i = 0; i < 8; ++i)
#pragma unroll
        for (int j = 0; j < 8; ++j) acc[i][j] = 0.f;

    const float* Aptr0 = A + (size_t)(bm + arow) * K + ak;
    const float* Aptr1 = A + (size_t)(bm + arow + 64) * K + ak;
    const float* Wptr0 = W + (size_t)wrow * N + bn + wcol;
    const float* Wptr1 = W + (size_t)(wrow + 8) * N + bn + wcol;

    for (int k0 = 0; k0 < K; k0 += 16) {
        float4 a0 = *(const float4*)(Aptr0 + k0);
        float4 a1 = *(const float4*)(Aptr1 + k0);
        float4 w0 = *(const float4*)(Wptr0 + (size_t)k0 * N);
        float4 w1 = *(const float4*)(Wptr1 + (size_t)k0 * N);

        As[ak + 0][arow] = a0.x; As[ak + 1][arow] = a0.y;
        As[ak + 2][arow] = a0.z; As[ak + 3][arow] = a0.w;
        As[ak + 0][arow + 64] = a1.x; As[ak + 1][arow + 64] = a1.y;
        As[ak + 2][arow + 64] = a1.z; As[ak + 3][arow + 64] = a1.w;
        *(float4*)&Ws[wrow][wcol]     = w0;
        *(float4*)&Ws[wrow + 8][wcol] = w1;
        __syncthreads();

#pragma unroll
        for (int kk = 0; kk < 16; ++kk) {
            float a[8], b[8];
            *(float4*)(a)     = *(const float4*)&As[kk][ty * 4];
            *(float4*)(a + 4) = *(const float4*)&As[kk][ty * 4 + 64];
            *(float4*)(b)     = *(const float4*)&Ws[kk][tx * 4];
            *(float4*)(b + 4) = *(const float4*)&Ws[kk][tx * 4 + 64];
#pragma unroll
            for (int i = 0; i < 8; ++i)
#pragma unroll
                for (int j = 0; j < 8; ++j)
                    acc[i][j] = fmaf(a[i], b[j], acc[i][j]);
        }
        __syncthreads();
    }

    float bvv[8];
#pragma unroll
    for (int jh = 0; jh < 2; ++jh)
#pragma unroll
        for (int j = 0; j < 4; ++j)
            bvv[jh * 4 + j] = bias ? bias[bn + jh * 64 + tx * 4 + j] : 0.f;

#pragma unroll
    for (int i = 0; i < 8; ++i) {
        int row = bm + ((i < 4) ? (ty * 4 + i) : (64 + ty * 4 + i - 4));
#pragma unroll
        for (int jh = 0; jh < 2; ++jh) {
            float4 r;
            r.x = (acc[i][jh * 4 + 0] + bvv[jh * 4 + 0]) * outScale;
            r.y = (acc[i][jh * 4 + 1] + bvv[jh * 4 + 1]) * outScale;
            r.z = (acc[i][jh * 4 + 2] + bvv[jh * 4 + 2]) * outScale;
            r.w = (acc[i][jh * 4 + 3] + bvv[jh * 4 + 3]) * outScale;
            *(float4*)(C + (size_t)row * N + bn + jh * 64 + tx * 4) = r;
        }
    }
}

// ---------------------------------------------------------------------------
// Causal flash attention, fp32.
// grid = (T/64 q-tiles, B*H). block = 256 (16x16). Each block: 64 queries of
// one (b,h). Online softmax over key tiles 0..qt (causal tile skip).
// Q is pre-scaled by QK_SCALE (done in the q projection epilogue);
// K is scaled by QK_SCALE on load, matching the reference exactly.
// ---------------------------------------------------------------------------
__global__ __launch_bounds__(256)
void attn_kernel(const float* __restrict__ Q, const float* __restrict__ Kb,
                 const float* __restrict__ Vb, float* __restrict__ O)
{
    extern __shared__ float sh[];
    float* Qs = sh;                 // [64][65]  Qs[kd*65 + token]
    float* Ks = Qs + 64 * 65;       // [64][65]  Ks[kd*65 + token]; reused as P^T[c*65 + r]
    float* Vs = Ks + 64 * 65;       // [64][64]  Vs[token*64 + kd]

    const int qt  = blockIdx.x;
    const int bh  = blockIdx.y;
    const int b   = bh >> 4;
    const int h   = bh & 15;
    const int tid = threadIdx.x;
    const int ty  = tid >> 4;
    const int tx  = tid & 15;
    const int q0  = qt * 64;
    const size_t base = (size_t)b * TT * DD + (size_t)h * DHH;

    // Load Q tile transposed into shared (already scaled).
    for (int l = tid; l < 64 * 64; l += 256) {
        int r = l >> 6;     // token in tile
        int c = l & 63;     // head dim (coalesced global)
        Qs[c * 65 + r] = Q[base + (size_t)(q0 + r) * DD + c];
    }

    float m_i[4], l_i[4], acc[4][4];
#pragma unroll
    for (int i = 0; i < 4; ++i) {
        m_i[i] = -3.0e38f;
        l_i[i] = 0.f;
#pragma unroll
        for (int j = 0; j < 4; ++j) acc[i][j] = 0.f;
    }
    __syncthreads();

    for (int jt = 0; jt <= qt; ++jt) {
        const int k0 = jt * 64;
        // Load K tile transposed + scaled; V tile direct (float4).
        for (int l = tid; l < 64 * 64; l += 256) {
            int r = l >> 6;
            int c = l & 63;
            Ks[c * 65 + r] = Kb[base + (size_t)(k0 + r) * DD + c] * QK_SCALE;
        }
        for (int l = tid; l < 64 * 16; l += 256) {
            int r  = l >> 4;
            int c4 = (l & 15) << 2;
            *(float4*)&Vs[r * 64 + c4] =
                *(const float4*)(Vb + base + (size_t)(k0 + r) * DD + c4);
        }
        __syncthreads();

        // S = Q K^T (thread owns 4x4 of the 64x64 tile)
        float s[4][4];
#pragma unroll
        for (int i = 0; i < 4; ++i)
#pragma unroll
            for (int j = 0; j < 4; ++j) s[i][j] = 0.f;

#pragma unroll 8
        for (int kk = 0; kk < 64; ++kk) {
            float a0 = Qs[kk * 65 + ty * 4 + 0];
            float a1 = Qs[kk * 65 + ty * 4 + 1];
            float a2 = Qs[kk * 65 + ty * 4 + 2];
            float a3 = Qs[kk * 65 + ty * 4 + 3];
            float b0 = Ks[kk * 65 + tx * 4 + 0];
            float b1 = Ks[kk * 65 + tx * 4 + 1];
            float b2 = Ks[kk * 65 + tx * 4 + 2];
            float b3 = Ks[kk * 65 + tx * 4 + 3];
            s[0][0] = fmaf(a0, b0, s[0][0]); s[0][1] = fmaf(a0, b1, s[0][1]);
            s[0][2] = fmaf(a0, b2, s[0][2]); s[0][3] = fmaf(a0, b3, s[0][3]);
            s[1][0] = fmaf(a1, b0, s[1][0]); s[1][1] = fmaf(a1, b1, s[1][1]);
            s[1][2] = fmaf(a1, b2, s[1][2]); s[1][3] = fmaf(a1, b3, s[1][3]);
            s[2][0] = fmaf(a2, b0, s[2][0]); s[2][1] = fmaf(a2, b1, s[2][1]);
            s[2][2] = fmaf(a2, b2, s[2][2]); s[2][3] = fmaf(a2, b3, s[2][3]);
            s[3][0] = fmaf(a3, b0, s[3][0]); s[3][1] = fmaf(a3, b1, s[3][1]);
            s[3][2] = fmaf(a3, b2, s[3][2]); s[3][3] = fmaf(a3, b3, s[3][3]);
        }

        // Causal mask on the diagonal tile (same value the reference adds).
        if (jt == qt) {
#pragma unroll
            for (int i = 0; i < 4; ++i)
#pragma unroll
                for (int j = 0; j < 4; ++j)
                    if (tx * 4 + j > ty * 4 + i) s[i][j] += -1e9f;
        }

        // Online softmax stats (rows owned jointly by 16 lanes of same ty).
        float alpha[4];
#pragma unroll
        for (int i = 0; i < 4; ++i) {
            float v = fmaxf(fmaxf(s[i][0], s[i][1]), fmaxf(s[i][2], s[i][3]));
#pragma unroll
            for (int o = 1; o < 16; o <<= 1)
                v = fmaxf(v, __shfl_xor_sync(0xffffffffu, v, o, 32));
            float mt = fmaxf(m_i[i], v);
            alpha[i] = __expf(m_i[i] - mt);
            m_i[i] = mt;
        }

        float p[4][4];
#pragma unroll
        for (int i = 0; i < 4; ++i) {
            float rs = 0.f;
#pragma unroll
            for (int j = 0; j < 4; ++j) {
                p[i][j] = __expf(s[i][j] - m_i[i]);
                rs += p[i][j];
            }
            l_i[i] = l_i[i] * alpha[i] + rs;
        }

        __syncthreads();   // all lanes done reading Ks before overwrite with P^T
#pragma unroll
        for (int j = 0; j < 4; ++j)
#pragma unroll
            for (int i = 0; i < 4; ++i)
                Ks[(tx * 4 + j) * 65 + ty * 4 + i] = p[i][j];
        __syncthreads();

        // O = O*alpha + P @ V
#pragma unroll
        for (int i = 0; i < 4; ++i)
#pragma unroll
            for (int j = 0; j < 4; ++j) acc[i][j] *= alpha[i];

#pragma unroll 8
        for (int c = 0; c < 64; ++c) {
            float pa0 = Ks[c * 65 + ty * 4 + 0];
            float pa1 = Ks[c * 65 + ty * 4 + 1];
            float pa2 = Ks[c * 65 + ty * 4 + 2];
            float pa3 = Ks[c * 65 + ty * 4 + 3];
            float vb0 = Vs[c * 64 + tx * 4 + 0];
            float vb1 = Vs[c * 64 + tx * 4 + 1];
            float vb2 = Vs[c * 64 + tx * 4 + 2];
            float vb3 = Vs[c * 64 + tx * 4 + 3];
            acc[0][0] = fmaf(pa0, vb0, acc[0][0]); acc[0][1] = fmaf(pa0, vb1, acc[0][1]);
            acc[0][2] = fmaf(pa0, vb2, acc[0][2]); acc[0][3] = fmaf(pa0, vb3, acc[0][3]);
            acc[1][0] = fmaf(pa1, vb0, acc[1][0]); acc[1][1] = fmaf(pa1, vb1, acc[1][1]);
            acc[1][2] = fmaf(pa1, vb2, acc[1][2]); acc[1][3] = fmaf(pa1, vb3, acc[1][3]);
            acc[2][0] = fmaf(pa2, vb0, acc[2][0]); acc[2][1] = fmaf(pa2, vb1, acc[2][1]);
            acc[2][2] = fmaf(pa2, vb2, acc[2][2]); acc[2][3] = fmaf(pa2, vb3, acc[2][3]);
            acc[3][0] = fmaf(pa3, vb0, acc[3][0]); acc[3][1] = fmaf(pa3, vb1, acc[3][1]);
            acc[3][2] = fmaf(pa3, vb2, acc[3][2]); acc[3][3] = fmaf(pa3, vb3, acc[3][3]);
        }
        __syncthreads();   // done reading Ks/Vs before next tile's loads
    }

    // Reduce l across the 16 lanes owning each row, normalize, store.
#pragma unroll
    for (int i = 0; i < 4; ++i) {
#pragma unroll
        for (int o = 1; o < 16; o <<= 1)
            l_i[i] += __shfl_xor_sync(0xffffffffu, l_i[i], o, 32);
    }
#pragma unroll
    for (int i = 0; i < 4; ++i) {
        float inv = 1.0f / l_i[i];
        float4 r;
        r.x = acc[i][0] * inv;
        r.y = acc[i][1] * inv;
        r.z = acc[i][2] * inv;
        r.w = acc[i][3] * inv;
        *(float4*)(O + base + (size_t)(q0 + ty * 4 + i) * DD + tx * 4) = r;
    }
}

// ---------------------------------------------------------------------------
// Launch: q/k/v projections -> attention -> output projection.
// Inputs (metadata order): x, k_cache, v_cache, mask, Wq, bq, Wk, Wv, bv, Wo, bo
// Output: [out (BT*D) | k_cache (BT*D) | v_cache (BT*D)] (k/v fully overwritten
// by the projections since T_new == T_cache).
// ---------------------------------------------------------------------------
extern "C" void kernel_launch(void* const* d_in, const int* in_sizes, int n_in,
                              void* d_out, int out_size)
{
    (void)in_sizes; (void)n_in;
    const float* x  = (const float*)d_in[0];
    const float* Wq = (const float*)d_in[4];
    const float* bq = (const float*)d_in[5];
    const float* Wk = (const float*)d_in[6];
    const float* Wv = (const float*)d_in[7];
    const float* bv = (const float*)d_in[8];
    const float* Wo = (const float*)d_in[9];
    const float* bo = (const float*)d_in[10];
    float* out = (float*)d_out;

    float *qp, *ap, *kfp, *vfp;
    cudaGetSymbolAddress((void**)&qp,  g_q);
    cudaGetSymbolAddress((void**)&ap,  g_attn);
    cudaGetSymbolAddress((void**)&kfp, g_kfall);
    cudaGetSymbolAddress((void**)&vfp, g_vfall);

    const size_t btd = (size_t)BT * DD;
    float* kdst = kfp;
    float* vdst = vfp;
    if ((size_t)out_size >= 3 * btd) {
        kdst = out + btd;
        vdst = out + 2 * btd;
    }

    dim3 ggrid(DD / 128, BT / 128);   // (8, 28)

    // q = (x@Wq + bq) * scale   (scale folded into epilogue)
    sgemm_bias_kernel<<<ggrid, 256>>>(x, Wq, bq, qp, BT, DD, DD, QK_SCALE);
    // k = x@Wk  (unscaled; becomes k_cache output)
    sgemm_bias_kernel<<<ggrid, 256>>>(x, Wk, nullptr, kdst, BT, DD, DD, 1.0f);
    // v = x@Wv + bv  (becomes v_cache output)
    sgemm_bias_kernel<<<ggrid, 256>>>(x, Wv, bv, vdst, BT, DD, DD, 1.0f);

    // attention
    const int shmem = (64 * 65 + 64 * 65 + 64 * 64) * (int)sizeof(float); // 49664
    cudaFuncSetAttribute(attn_kernel, cudaFuncAttributeMaxDynamicSharedMemorySize, shmem);
    attn_kernel<<<dim3(TT / 64, BB * HH), 256, shmem>>>(qp, kdst, vdst, ap);

    // out = attn@Wo + bo
    sgemm_bias_kernel<<<ggrid, 256>>>(ap, Wo, bo, out, BT, DD, DD, 1.0f);
}

// round 3
// speedup vs baseline: 2.0745x; 2.0745x over previous
#include <cuda_runtime.h>
#include <cuda_bf16.h>
#include <cstdint>
#include <cstddef>

// Problem constants
#define BB   8
#define TT   448
#define DD   1024
#define HH   16
#define DHH  64
#define BT   (BB * TT)              // 3584
#define QK_SCALE 0.35355339059327373f   // 64^(-0.25)

// GEMM tiling (mma.sync path)
#define BM 128
#define BN 128
#define BK 32
#define NCHUNKS (DD / BK)           // 32
#define PADE 40                     // padded row stride in bf16 elems
#define MAT_BYTES (128 * PADE * 2)  // 10240 per matrix tile
#define STG_BYTES (4 * MAT_BYTES)   // 40960 per stage
#define GEMM_SMEM (2 * STG_BYTES)   // 81920

// Scratch (allocation-free rule: __device__ globals)
__device__ float g_q[(size_t)BT * DD];
__device__ float g_attn[(size_t)BT * DD];
__device__ float g_kfall[(size_t)BT * DD];
__device__ float g_vfall[(size_t)BT * DD];
__device__ __nv_bfloat16 g_split_hi[(size_t)BT * DD];   // A-operand hi (x, then attn-out)
__device__ __nv_bfloat16 g_split_lo[(size_t)BT * DD];
__device__ __nv_bfloat16 g_wt_hi[4][(size_t)DD * DD];   // W^T hi, [n][k]
__device__ __nv_bfloat16 g_wt_lo[4][(size_t)DD * DD];

// ---------------------------------------------------------------------------
// PTX helpers (all plain sm_80+ ISA — compiles on compute_103)
// ---------------------------------------------------------------------------
__device__ __forceinline__ uint32_t smem_u32(const void* p) {
    uint32_t a;
    asm("{ .reg .u64 t; cvta.to.shared.u64 t, %1; cvt.u32.u64 %0, t; }" : "=r"(a) : "l"(p));
    return a;
}
__device__ __forceinline__ void cpasync16(uint32_t dst, const void* src) {
    asm volatile("cp.async.cg.shared.global [%0], [%1], 16;" :: "r"(dst), "l"(src));
}
#define CP_COMMIT() asm volatile("cp.async.commit_group;" ::: "memory")
#define CP_WAIT0()  asm volatile("cp.async.wait_group 0;" ::: "memory")

__device__ __forceinline__ void ldsm_x4(uint32_t* r, uint32_t a) {
    asm volatile("ldmatrix.sync.aligned.m8n8.x4.shared.b16 {%0,%1,%2,%3}, [%4];"
        : "=r"(r[0]), "=r"(r[1]), "=r"(r[2]), "=r"(r[3]) : "r"(a));
}
__device__ __forceinline__ void ldsm_x2(uint32_t* r, uint32_t a) {
    asm volatile("ldmatrix.sync.aligned.m8n8.x2.shared.b16 {%0,%1}, [%2];"
        : "=r"(r[0]), "=r"(r[1]) : "r"(a));
}
__device__ __forceinline__ void mma16816(float* d, const uint32_t* a, const uint32_t* b) {
    asm volatile("mma.sync.aligned.m16n8k16.row.col.f32.bf16.bf16.f32 "
        "{%0,%1,%2,%3}, {%4,%5,%6,%7}, {%8,%9}, {%0,%1,%2,%3};"
        : "+f"(d[0]), "+f"(d[1]), "+f"(d[2]), "+f"(d[3])
        : "r"(a[0]), "r"(a[1]), "r"(a[2]), "r"(a[3]), "r"(b[0]), "r"(b[1]));
}

// ---------------------------------------------------------------------------
// fp32 -> bf16 hi/lo split (elementwise), 4 floats/thread
// ---------------------------------------------------------------------------
__global__ __launch_bounds__(256)
void split_kernel(const float* __restrict__ in,
                  __nv_bfloat16* __restrict__ hi, __nv_bfloat16* __restrict__ lo)
{
    const size_t i = ((size_t)blockIdx.x * 256 + threadIdx.x) * 4;
    float4 v = *(const float4*)(in + i);
    __nv_bfloat162 h01, h23, l01, l23;
    h01.x = __float2bfloat16(v.x); h01.y = __float2bfloat16(v.y);
    h23.x = __float2bfloat16(v.z); h23.y = __float2bfloat16(v.w);
    l01.x = __float2bfloat16(v.x - __bfloat162float(h01.x));
    l01.y = __float2bfloat16(v.y - __bfloat162float(h01.y));
    l23.x = __float2bfloat16(v.z - __bfloat162float(h23.x));
    l23.y = __float2bfloat16(v.w - __bfloat162float(h23.y));
    uint2 hp, lp;
    hp.x = *(uint32_t*)&h01; hp.y = *(uint32_t*)&h23;
    lp.x = *(uint32_t*)&l01; lp.y = *(uint32_t*)&l23;
    *(uint2*)(hi + i) = hp;
    *(uint2*)(lo + i) = lp;
}

// ---------------------------------------------------------------------------
// Weight transpose + bf16 hi/lo split: W[K,N] fp32 -> Wt_hi/lo[N,K] bf16
// ---------------------------------------------------------------------------
__global__ __launch_bounds__(256)
void wconv_kernel(const float* __restrict__ W,
                  __nv_bfloat16* __restrict__ hi, __nv_bfloat16* __restrict__ lo)
{
    __shared__ float t[32][33];
    const int k0 = blockIdx.y * 32, n0 = blockIdx.x * 32;
    const int tx = threadIdx.x & 31, ty = threadIdx.x >> 5;   // ty 0..7
#pragma unroll
    for (int i = 0; i < 4; ++i)
        t[ty + i * 8][tx] = W[(size_t)(k0 + ty + i * 8) * DD + n0 + tx];
    __syncthreads();
#pragma unroll
    for (int i = 0; i < 4; ++i) {
        const int n = n0 + ty + i * 8, k = k0 + tx;
        float v = t[tx][ty + i * 8];
        __nv_bfloat16 h = __float2bfloat16(v);
        __nv_bfloat16 l = __float2bfloat16(v - __bfloat162float(h));
        hi[(size_t)n * DD + k] = h;
        lo[(size_t)n * DD + k] = l;
    }
}

// ---------------------------------------------------------------------------
// 3xBF16-split GEMM via mma.sync.m16n8k16.
// C[row, colG] = sum_k A[row,k] * B[colG,k]   (B = W^T, [N][K] bf16 hi/lo)
// colG in [0, gridDim.x*128); mat = colG>>10 selects (dst, bias, scale) —
// used to fuse the q/k/v projections as one N=3072 GEMM.
// CTA 128x128, BK=32, 256 threads (8 warps as 2x4), cp.async double buffer.
// ---------------------------------------------------------------------------
__global__ __launch_bounds__(256)
void gemm_mma_kernel(const __nv_bfloat16* __restrict__ Ahi,
                     const __nv_bfloat16* __restrict__ Alo,
                     const __nv_bfloat16* __restrict__ Bhi,
                     const __nv_bfloat16* __restrict__ Blo,
                     float* __restrict__ d0, float* __restrict__ d1, float* __restrict__ d2,
                     const float* __restrict__ bias0, const float* __restrict__ bias1,
                     const float* __restrict__ bias2,
                     float s0, float s1, float s2)
{
    extern __shared__ char smem[];
    const uint32_t sb = smem_u32(smem);
    const int tid  = threadIdx.x;
    const int lane = tid & 31;
    const int wid  = tid >> 5;
    const int warp_m = wid >> 2;      // 0..1  -> 64 rows each
    const int warp_n = wid & 3;       // 0..3  -> 32 cols each
    const int bm  = blockIdx.y * BM;
    const int bnG = blockIdx.x * BN;

    float acc[4][4][4];
#pragma unroll
    for (int i = 0; i < 4; ++i)
#pragma unroll
        for (int j = 0; j < 4; ++j)
#pragma unroll
            for (int q = 0; q < 4; ++q) acc[i][j][q] = 0.f;

    // ---- loader: 8 cp.async(16B) per thread per chunk ----
    const int lrow = tid >> 2;              // 0..63
    const int lseg = (tid & 3) * 8;         // bf16 elems (16B)
    const __nv_bfloat16* srcA0 = Ahi + (size_t)bm  * DD + lseg;
    const __nv_bfloat16* srcA1 = Alo + (size_t)bm  * DD + lseg;
    const __nv_bfloat16* srcB0 = Bhi + (size_t)bnG * DD + lseg;
    const __nv_bfloat16* srcB1 = Blo + (size_t)bnG * DD + lseg;

    auto load_chunk = [&](int c, int s) {
        const int k0 = c * BK;
        const uint32_t dbase = sb + s * STG_BYTES;
#pragma unroll
        for (int i = 0; i < 2; ++i) {
            const int row = lrow + i * 64;
            const size_t goff = (size_t)row * DD + k0;
            const uint32_t soff = (uint32_t)(row * PADE + lseg) * 2;
            cpasync16(dbase + 0 * MAT_BYTES + soff, srcA0 + goff);
            cpasync16(dbase + 1 * MAT_BYTES + soff, srcA1 + goff);
            cpasync16(dbase + 2 * MAT_BYTES + soff, srcB0 + goff);
            cpasync16(dbase + 3 * MAT_BYTES + soff, srcB1 + goff);
        }
    };

    // ---- ldmatrix per-lane base offsets (bf16 elem units) ----
    const int arow = warp_m * 64 + (lane & 7) + ((lane >> 3) & 1) * 8;
    const int acol = (lane >> 4) * 8;
    const int brow = warp_n * 32 + (lane & 7);
    const int bcol = ((lane >> 3) & 1) * 8;    // lanes >=16 unused by x2

    load_chunk(0, 0);
    CP_COMMIT();

    for (int c = 0; c < NCHUNKS; ++c) {
        CP_WAIT0();
        __syncthreads();
        if (c + 1 < NCHUNKS) {
            load_chunk(c + 1, (c + 1) & 1);
            CP_COMMIT();
        }
        const uint32_t st = sb + (c & 1) * STG_BYTES;

#pragma unroll
        for (int k16 = 0; k16 < BK; k16 += 16) {
            uint32_t bh[4][2], bl[4][2];
#pragma unroll
            for (int nf = 0; nf < 4; ++nf) {
                const uint32_t bo = (uint32_t)((brow + nf * 8) * PADE + bcol + k16) * 2;
                ldsm_x2(bh[nf], st + 2 * MAT_BYTES + bo);
                ldsm_x2(bl[nf], st + 3 * MAT_BYTES + bo);
            }
#pragma unroll
            for (int mf = 0; mf < 4; ++mf) {
                uint32_t ah[4], al[4];
                const uint32_t ao = (uint32_t)((arow + mf * 16) * PADE + acol + k16) * 2;
                ldsm_x4(ah, st + 0 * MAT_BYTES + ao);
                ldsm_x4(al, st + 1 * MAT_BYTES + ao);
#pragma unroll
                for (int nf = 0; nf < 4; ++nf) {
                    mma16816(acc[mf][nf], ah, bh[nf]);
                    mma16816(acc[mf][nf], ah, bl[nf]);
                    mma16816(acc[mf][nf], al, bh[nf]);
                }
            }
        }
    }

    // ---- epilogue ----
    const int mat = bnG >> 10;
    float* dst = (mat == 0) ? d0 : ((mat == 1) ? d1 : d2);
    const float* bias = (mat == 0) ? bias0 : ((mat == 1) ? bias1 : bias2);
    const float scale = (mat == 0) ? s0 : ((mat == 1) ? s1 : s2);
    const int bn = bnG & (DD - 1);

#pragma unroll
    for (int mf = 0; mf < 4; ++mf) {
        const int row = bm + warp_m * 64 + mf * 16 + (lane >> 2);
#pragma unroll
        for (int nf = 0; nf < 4; ++nf) {
            const int col = bn + warp_n * 32 + nf * 8 + (lane & 3) * 2;
            const float b0 = bias ? bias[col] : 0.f;
            const float b1 = bias ? bias[col + 1] : 0.f;
            float2 v0, v1;
            v0.x = (acc[mf][nf][0] + b0) * scale;
            v0.y = (acc[mf][nf][1] + b1) * scale;
            v1.x = (acc[mf][nf][2] + b0) * scale;
            v1.y = (acc[mf][nf][3] + b1) * scale;
            *(float2*)(dst + (size_t)row * DD + col) = v0;
            *(float2*)(dst + (size_t)(row + 8) * DD + col) = v1;
        }
    }
}

// ---------------------------------------------------------------------------
// Causal flash attention, fp32 (unchanged; 166us)
// ---------------------------------------------------------------------------
__global__ __launch_bounds__(256)
void attn_kernel(const float* __restrict__ Q, const float* __restrict__ Kb,
                 const float* __restrict__ Vb, float* __restrict__ O)
{
    extern __shared__ float sh[];
    float* Qs = sh;
    float* Ks = Qs + 64 * 65;
    float* Vs = Ks + 64 * 65;

    const int qt  = blockIdx.x;
    const int bh  = blockIdx.y;
    const int b   = bh >> 4;
    const int h   = bh & 15;
    const int tid = threadIdx.x;
    const int ty  = tid >> 4;
    const int tx  = tid & 15;
    const int q0  = qt * 64;
    const size_t base = (size_t)b * TT * DD + (size_t)h * DHH;

    for (int l = tid; l < 64 * 64; l += 256) {
        int r = l >> 6;
        int c = l & 63;
        Qs[c * 65 + r] = Q[base + (size_t)(q0 + r) * DD + c];
    }

    float m_i[4], l_i[4], acc[4][4];
#pragma unroll
    for (int i = 0; i < 4; ++i) {
        m_i[i] = -3.0e38f;
        l_i[i] = 0.f;
#pragma unroll
        for (int j = 0; j < 4; ++j) acc[i][j] = 0.f;
    }
    __syncthreads();

    for (int jt = 0; jt <= qt; ++jt) {
        const int k0 = jt * 64;
        for (int l = tid; l < 64 * 64; l += 256) {
            int r = l >> 6;
            int c = l & 63;
            Ks[c * 65 + r] = Kb[base + (size_t)(k0 + r) * DD + c] * QK_SCALE;
        }
        for (int l = tid; l < 64 * 16; l += 256) {
            int r  = l >> 4;
            int c4 = (l & 15) << 2;
            *(float4*)&Vs[r * 64 + c4] =
                *(const float4*)(Vb + base + (size_t)(k0 + r) * DD + c4);
        }
        __syncthreads();

        float s[4][4];
#pragma unroll
        for (int i = 0; i < 4; ++i)
#pragma unroll
            for (int j = 0; j < 4; ++j) s[i][j] = 0.f;

#pragma unroll 8
        for (int kk = 0; kk < 64; ++kk) {
            float a0 = Qs[kk * 65 + ty * 4 + 0];
            float a1 = Qs[kk * 65 + ty * 4 + 1];
            float a2 = Qs[kk * 65 + ty * 4 + 2];
            float a3 = Qs[kk * 65 + ty * 4 + 3];
            float b0 = Ks[kk * 65 + tx * 4 + 0];
            float b1 = Ks[kk * 65 + tx * 4 + 1];
            float b2 = Ks[kk * 65 + tx * 4 + 2];
            float b3 = Ks[kk * 65 + tx * 4 + 3];
            s[0][0] = fmaf(a0, b0, s[0][0]); s[0][1] = fmaf(a0, b1, s[0][1]);
            s[0][2] = fmaf(a0, b2, s[0][2]); s[0][3] = fmaf(a0, b3, s[0][3]);
            s[1][0] = fmaf(a1, b0, s[1][0]); s[1][1] = fmaf(a1, b1, s[1][1]);
            s[1][2] = fmaf(a1, b2, s[1][2]); s[1][3] = fmaf(a1, b3, s[1][3]);
            s[2][0] = fmaf(a2, b0, s[2][0]); s[2][1] = fmaf(a2, b1, s[2][1]);
            s[2][2] = fmaf(a2, b2, s[2][2]); s[2][3] = fmaf(a2, b3, s[2][3]);
            s[3][0] = fmaf(a3, b0, s[3][0]); s[3][1] = fmaf(a3, b1, s[3][1]);
            s[3][2] = fmaf(a3, b2, s[3][2]); s[3][3] = fmaf(a3, b3, s[3][3]);
        }

        if (jt == qt) {
#pragma unroll
            for (int i = 0; i < 4; ++i)
#pragma unroll
                for (int j = 0; j < 4; ++j)
                    if (tx * 4 + j > ty * 4 + i) s[i][j] += -1e9f;
        }

        float alpha[4];
#pragma unroll
        for (int i = 0; i < 4; ++i) {
            float v = fmaxf(fmaxf(s[i][0], s[i][1]), fmaxf(s[i][2], s[i][3]));
#pragma unroll
            for (int o = 1; o < 16; o <<= 1)
                v = fmaxf(v, __shfl_xor_sync(0xffffffffu, v, o, 32));
            float mt = fmaxf(m_i[i], v);
            alpha[i] = __expf(m_i[i] - mt);
            m_i[i] = mt;
        }

        float p[4][4];
#pragma unroll
        for (int i = 0; i < 4; ++i) {
            float rs = 0.f;
#pragma unroll
            for (int j = 0; j < 4; ++j) {
                p[i][j] = __expf(s[i][j] - m_i[i]);
                rs += p[i][j];
            }
            l_i[i] = l_i[i] * alpha[i] + rs;
        }

        __syncthreads();
#pragma unroll
        for (int j = 0; j < 4; ++j)
#pragma unroll
            for (int i = 0; i < 4; ++i)
                Ks[(tx * 4 + j) * 65 + ty * 4 + i] = p[i][j];
        __syncthreads();

#pragma unroll
        for (int i = 0; i < 4; ++i)
#pragma unroll
            for (int j = 0; j < 4; ++j) acc[i][j] *= alpha[i];

#pragma unroll 8
        for (int c = 0; c < 64; ++c) {
            float pa0 = Ks[c * 65 + ty * 4 + 0];
            float pa1 = Ks[c * 65 + ty * 4 + 1];
            float pa2 = Ks[c * 65 + ty * 4 + 2];
            float pa3 = Ks[c * 65 + ty * 4 + 3];
            float vb0 = Vs[c * 64 + tx * 4 + 0];
            float vb1 = Vs[c * 64 + tx * 4 + 1];
            float vb2 = Vs[c * 64 + tx * 4 + 2];
            float vb3 = Vs[c * 64 + tx * 4 + 3];
            acc[0][0] = fmaf(pa0, vb0, acc[0][0]); acc[0][1] = fmaf(pa0, vb1, acc[0][1]);
            acc[0][2] = fmaf(pa0, vb2, acc[0][2]); acc[0][3] = fmaf(pa0, vb3, acc[0][3]);
            acc[1][0] = fmaf(pa1, vb0, acc[1][0]); acc[1][1] = fmaf(pa1, vb1, acc[1][1]);
            acc[1][2] = fmaf(pa1, vb2, acc[1][2]); acc[1][3] = fmaf(pa1, vb3, acc[1][3]);
            acc[2][0] = fmaf(pa2, vb0, acc[2][0]); acc[2][1] = fmaf(pa2, vb1, acc[2][1]);
            acc[2][2] = fmaf(pa2, vb2, acc[2][2]); acc[2][3] = fmaf(pa2, vb3, acc[2][3]);
            acc[3][0] = fmaf(pa3, vb0, acc[3][0]); acc[3][1] = fmaf(pa3, vb1, acc[3][1]);
            acc[3][2] = fmaf(pa3, vb2, acc[3][2]); acc[3][3] = fmaf(pa3, vb3, acc[3][3]);
        }
        __syncthreads();
    }

#pragma unroll
    for (int i = 0; i < 4; ++i) {
#pragma unroll
        for (int o = 1; o < 16; o <<= 1)
            l_i[i] += __shfl_xor_sync(0xffffffffu, l_i[i], o, 32);
    }
#pragma unroll
    for (int i = 0; i < 4; ++i) {
        float inv = 1.0f / l_i[i];
        float4 r;
        r.x = acc[i][0] * inv;
        r.y = acc[i][1] * inv;
        r.z = acc[i][2] * inv;
        r.w = acc[i][3] * inv;
        *(float4*)(O + base + (size_t)(q0 + ty * 4 + i) * DD + tx * 4) = r;
    }
}

// ---------------------------------------------------------------------------
// Launch
// Inputs: x, k_cache, v_cache, mask, Wq, bq, Wk, Wv, bv, Wo, bo
// Output: [out | k_cache | v_cache]
// ---------------------------------------------------------------------------
extern "C" void kernel_launch(void* const* d_in, const int* in_sizes, int n_in,
                              void* d_out, int out_size)
{
    (void)in_sizes; (void)n_in;
    const float* x  = (const float*)d_in[0];
    const float* Wq = (const float*)d_in[4];
    const float* bq = (const float*)d_in[5];
    const float* Wk = (const float*)d_in[6];
    const float* Wv = (const float*)d_in[7];
    const float* bv = (const float*)d_in[8];
    const float* Wo = (const float*)d_in[9];
    const float* bo = (const float*)d_in[10];
    float* out = (float*)d_out;

    float *qp, *ap, *kfp, *vfp;
    __nv_bfloat16 *shi, *slo, *whi, *wlo;
    cudaGetSymbolAddress((void**)&qp,  g_q);
    cudaGetSymbolAddress((void**)&ap,  g_attn);
    cudaGetSymbolAddress((void**)&kfp, g_kfall);
    cudaGetSymbolAddress((void**)&vfp, g_vfall);
    cudaGetSymbolAddress((void**)&shi, g_split_hi);
    cudaGetSymbolAddress((void**)&slo, g_split_lo);
    cudaGetSymbolAddress((void**)&whi, g_wt_hi);
    cudaGetSymbolAddress((void**)&wlo, g_wt_lo);

    const size_t btd = (size_t)BT * DD;
    const size_t wsz = (size_t)DD * DD;
    float* kdst = kfp;
    float* vdst = vfp;
    if ((size_t)out_size >= 3 * btd) {
        kdst = out + btd;
        vdst = out + 2 * btd;
    }

    // 1. weight transpose + split (Wq,Wk,Wv packed contiguously for fused QKV)
    dim3 wg(32, 32);
    wconv_kernel<<<wg, 256>>>(Wq, whi + 0 * wsz, wlo + 0 * wsz);
    wconv_kernel<<<wg, 256>>>(Wk, whi + 1 * wsz, wlo + 1 * wsz);
    wconv_kernel<<<wg, 256>>>(Wv, whi + 2 * wsz, wlo + 2 * wsz);
    wconv_kernel<<<wg, 256>>>(Wo, whi + 3 * wsz, wlo + 3 * wsz);

    // 2. split x
    split_kernel<<<(int)(btd / 1024), 256>>>(x, shi, slo);

    // 3. fused QKV projection: N = 3072 (mat0 -> q*scale+bq, mat1 -> k, mat2 -> v+bv)
    cudaFuncSetAttribute(gemm_mma_kernel, cudaFuncAttributeMaxDynamicSharedMemorySize, GEMM_SMEM);
    gemm_mma_kernel<<<dim3(3 * DD / BN, BT / BM), 256, GEMM_SMEM>>>(
        shi, slo, whi, wlo,
        qp, kdst, vdst, bq, nullptr, bv, QK_SCALE, 1.0f, 1.0f);

    // 4. attention
    const int shmem = (64 * 65 + 64 * 65 + 64 * 64) * (int)sizeof(float);
    cudaFuncSetAttribute(attn_kernel, cudaFuncAttributeMaxDynamicSharedMemorySize, shmem);
    attn_kernel<<<dim3(TT / 64, BB * HH), 256, shmem>>>(qp, kdst, vdst, ap);

    // 5. split attn output, 6. output projection
    split_kernel<<<(int)(btd / 1024), 256>>>(ap, shi, slo);
    gemm_mma_kernel<<<dim3(DD / BN, BT / BM), 256, GEMM_SMEM>>>(
        shi, slo, whi + 3 * wsz, wlo + 3 * wsz,
        out, out, out, bo, bo, bo, 1.0f, 1.0f, 1.0f);
}

// round 4
// speedup vs baseline: 2.6133x; 1.2597x over previous
#include <cuda_runtime.h>
#include <cuda_bf16.h>
#include <cuda_fp16.h>
#include <cstdint>
#include <cstddef>

// Problem constants
#define BB   8
#define TT   448
#define DD   1024
#define HH   16
#define DHH  64
#define BT   (BB * TT)              // 3584
#define QK_SCALE 0.35355339059327373f   // 64^(-0.25)

// GEMM tiling (mma.sync path)
#define BM 128
#define BN 128
#define BK 32
#define NCHUNKS (DD / BK)           // 32
#define PADE 40                     // padded row stride in bf16 elems
#define MAT_BYTES (128 * PADE * 2)  // 10240 per matrix tile
#define STG_BYTES (4 * MAT_BYTES)   // 40960 per stage
#define GEMM_SMEM (2 * STG_BYTES)   // 81920

#define AT_PAD 72                   // attn smem row stride (halves)

// Scratch (allocation-free rule: __device__ globals)
__device__ float g_q[(size_t)BT * DD];
__device__ float g_attn[(size_t)BT * DD];
__device__ float g_kfall[(size_t)BT * DD];
__device__ float g_vfall[(size_t)BT * DD];
__device__ __nv_bfloat16 g_split_hi[(size_t)BT * DD];
__device__ __nv_bfloat16 g_split_lo[(size_t)BT * DD];
__device__ __nv_bfloat16 g_wt_hi[4][(size_t)DD * DD];   // W^T hi, [n][k]
__device__ __nv_bfloat16 g_wt_lo[4][(size_t)DD * DD];

// ---------------------------------------------------------------------------
// PTX helpers (plain sm_80+ ISA)
// ---------------------------------------------------------------------------
__device__ __forceinline__ uint32_t smem_u32(const void* p) {
    uint32_t a;
    asm("{ .reg .u64 t; cvta.to.shared.u64 t, %1; cvt.u32.u64 %0, t; }" : "=r"(a) : "l"(p));
    return a;
}
__device__ __forceinline__ void cpasync16(uint32_t dst, const void* src) {
    asm volatile("cp.async.cg.shared.global [%0], [%1], 16;" :: "r"(dst), "l"(src));
}
#define CP_COMMIT() asm volatile("cp.async.commit_group;" ::: "memory")
#define CP_WAIT0()  asm volatile("cp.async.wait_group 0;" ::: "memory")

__device__ __forceinline__ void ldsm_x4(uint32_t* r, uint32_t a) {
    asm volatile("ldmatrix.sync.aligned.m8n8.x4.shared.b16 {%0,%1,%2,%3}, [%4];"
        : "=r"(r[0]), "=r"(r[1]), "=r"(r[2]), "=r"(r[3]) : "r"(a));
}
__device__ __forceinline__ void ldsm_x2(uint32_t* r, uint32_t a) {
    asm volatile("ldmatrix.sync.aligned.m8n8.x2.shared.b16 {%0,%1}, [%2];"
        : "=r"(r[0]), "=r"(r[1]) : "r"(a));
}
__device__ __forceinline__ void mma16816(float* d, const uint32_t* a, const uint32_t* b) {
    asm volatile("mma.sync.aligned.m16n8k16.row.col.f32.bf16.bf16.f32 "
        "{%0,%1,%2,%3}, {%4,%5,%6,%7}, {%8,%9}, {%0,%1,%2,%3};"
        : "+f"(d[0]), "+f"(d[1]), "+f"(d[2]), "+f"(d[3])
        : "r"(a[0]), "r"(a[1]), "r"(a[2]), "r"(a[3]), "r"(b[0]), "r"(b[1]));
}
__device__ __forceinline__ void mma16816h(float* d, const uint32_t* a, const uint32_t* b) {
    asm volatile("mma.sync.aligned.m16n8k16.row.col.f32.f16.f16.f32 "
        "{%0,%1,%2,%3}, {%4,%5,%6,%7}, {%8,%9}, {%0,%1,%2,%3};"
        : "+f"(d[0]), "+f"(d[1]), "+f"(d[2]), "+f"(d[3])
        : "r"(a[0]), "r"(a[1]), "r"(a[2]), "r"(a[3]), "r"(b[0]), "r"(b[1]));
}

// ---------------------------------------------------------------------------
// fp32 -> bf16 hi/lo split (elementwise)
// ---------------------------------------------------------------------------
__global__ __launch_bounds__(256)
void split_kernel(const float* __restrict__ in,
                  __nv_bfloat16* __restrict__ hi, __nv_bfloat16* __restrict__ lo)
{
    const size_t i = ((size_t)blockIdx.x * 256 + threadIdx.x) * 4;
    float4 v = *(const float4*)(in + i);
    __nv_bfloat162 h01, h23, l01, l23;
    h01.x = __float2bfloat16(v.x); h01.y = __float2bfloat16(v.y);
    h23.x = __float2bfloat16(v.z); h23.y = __float2bfloat16(v.w);
    l01.x = __float2bfloat16(v.x - __bfloat162float(h01.x));
    l01.y = __float2bfloat16(v.y - __bfloat162float(h01.y));
    l23.x = __float2bfloat16(v.z - __bfloat162float(h23.x));
    l23.y = __float2bfloat16(v.w - __bfloat162float(h23.y));
    uint2 hp, lp;
    hp.x = *(uint32_t*)&h01; hp.y = *(uint32_t*)&h23;
    lp.x = *(uint32_t*)&l01; lp.y = *(uint32_t*)&l23;
    *(uint2*)(hi + i) = hp;
    *(uint2*)(lo + i) = lp;
}

// ---------------------------------------------------------------------------
// Weight transpose + bf16 hi/lo split, all 4 matrices in one launch (z dim)
// ---------------------------------------------------------------------------
__global__ __launch_bounds__(256)
void wconv4_kernel(const float* __restrict__ W0, const float* __restrict__ W1,
                   const float* __restrict__ W2, const float* __restrict__ W3,
                   __nv_bfloat16* __restrict__ hiB, __nv_bfloat16* __restrict__ loB)
{
    __shared__ float t[32][33];
    const int z = blockIdx.z;
    const float* W = (z == 0) ? W0 : (z == 1) ? W1 : (z == 2) ? W2 : W3;
    __nv_bfloat16* hi = hiB + (size_t)z * DD * DD;
    __nv_bfloat16* lo = loB + (size_t)z * DD * DD;
    const int k0 = blockIdx.y * 32, n0 = blockIdx.x * 32;
    const int tx = threadIdx.x & 31, ty = threadIdx.x >> 5;
#pragma unroll
    for (int i = 0; i < 4; ++i)
        t[ty + i * 8][tx] = W[(size_t)(k0 + ty + i * 8) * DD + n0 + tx];
    __syncthreads();
#pragma unroll
    for (int i = 0; i < 4; ++i) {
        const int n = n0 + ty + i * 8, k = k0 + tx;
        float v = t[tx][ty + i * 8];
        __nv_bfloat16 h = __float2bfloat16(v);
        __nv_bfloat16 l = __float2bfloat16(v - __bfloat162float(h));
        hi[(size_t)n * DD + k] = h;
        lo[(size_t)n * DD + k] = l;
    }
}

// ---------------------------------------------------------------------------
// 3xBF16-split GEMM via mma.sync (unchanged from R3; passes @342 TF/s-equiv)
// ---------------------------------------------------------------------------
__global__ __launch_bounds__(256)
void gemm_mma_kernel(const __nv_bfloat16* __restrict__ Ahi,
                     const __nv_bfloat16* __restrict__ Alo,
                     const __nv_bfloat16* __restrict__ Bhi,
                     const __nv_bfloat16* __restrict__ Blo,
                     float* __restrict__ d0, float* __restrict__ d1, float* __restrict__ d2,
                     const float* __restrict__ bias0, const float* __restrict__ bias1,
                     const float* __restrict__ bias2,
                     float s0, float s1, float s2)
{
    extern __shared__ char smem[];
    const uint32_t sb = smem_u32(smem);
    const int tid  = threadIdx.x;
    const int lane = tid & 31;
    const int wid  = tid >> 5;
    const int warp_m = wid >> 2;
    const int warp_n = wid & 3;
    const int bm  = blockIdx.y * BM;
    const int bnG = blockIdx.x * BN;

    float acc[4][4][4];
#pragma unroll
    for (int i = 0; i < 4; ++i)
#pragma unroll
        for (int j = 0; j < 4; ++j)
#pragma unroll
            for (int q = 0; q < 4; ++q) acc[i][j][q] = 0.f;

    const int lrow = tid >> 2;
    const int lseg = (tid & 3) * 8;
    const __nv_bfloat16* srcA0 = Ahi + (size_t)bm  * DD + lseg;
    const __nv_bfloat16* srcA1 = Alo + (size_t)bm  * DD + lseg;
    const __nv_bfloat16* srcB0 = Bhi + (size_t)bnG * DD + lseg;
    const __nv_bfloat16* srcB1 = Blo + (size_t)bnG * DD + lseg;

    auto load_chunk = [&](int c, int s) {
        const int k0 = c * BK;
        const uint32_t dbase = sb + s * STG_BYTES;
#pragma unroll
        for (int i = 0; i < 2; ++i) {
            const int row = lrow + i * 64;
            const size_t goff = (size_t)row * DD + k0;
            const uint32_t soff = (uint32_t)(row * PADE + lseg) * 2;
            cpasync16(dbase + 0 * MAT_BYTES + soff, srcA0 + goff);
            cpasync16(dbase + 1 * MAT_BYTES + soff, srcA1 + goff);
            cpasync16(dbase + 2 * MAT_BYTES + soff, srcB0 + goff);
            cpasync16(dbase + 3 * MAT_BYTES + soff, srcB1 + goff);
        }
    };

    const int arow = warp_m * 64 + (lane & 7) + ((lane >> 3) & 1) * 8;
    const int acol = (lane >> 4) * 8;
    const int brow = warp_n * 32 + (lane & 7);
    const int bcol = ((lane >> 3) & 1) * 8;

    load_chunk(0, 0);
    CP_COMMIT();

    for (int c = 0; c < NCHUNKS; ++c) {
        CP_WAIT0();
        __syncthreads();
        if (c + 1 < NCHUNKS) {
            load_chunk(c + 1, (c + 1) & 1);
            CP_COMMIT();
        }
        const uint32_t st = sb + (c & 1) * STG_BYTES;

#pragma unroll
        for (int k16 = 0; k16 < BK; k16 += 16) {
            uint32_t bh[4][2], bl[4][2];
#pragma unroll
            for (int nf = 0; nf < 4; ++nf) {
                const uint32_t bo = (uint32_t)((brow + nf * 8) * PADE + bcol + k16) * 2;
                ldsm_x2(bh[nf], st + 2 * MAT_BYTES + bo);
                ldsm_x2(bl[nf], st + 3 * MAT_BYTES + bo);
            }
#pragma unroll
            for (int mf = 0; mf < 4; ++mf) {
                uint32_t ah[4], al[4];
                const uint32_t ao = (uint32_t)((arow + mf * 16) * PADE + acol + k16) * 2;
                ldsm_x4(ah, st + 0 * MAT_BYTES + ao);
                ldsm_x4(al, st + 1 * MAT_BYTES + ao);
#pragma unroll
                for (int nf = 0; nf < 4; ++nf) {
                    mma16816(acc[mf][nf], ah, bh[nf]);
                    mma16816(acc[mf][nf], ah, bl[nf]);
                    mma16816(acc[mf][nf], al, bh[nf]);
                }
            }
        }
    }

    const int mat = bnG >> 10;
    float* dst = (mat == 0) ? d0 : ((mat == 1) ? d1 : d2);
    const float* bias = (mat == 0) ? bias0 : ((mat == 1) ? bias1 : bias2);
    const float scale = (mat == 0) ? s0 : ((mat == 1) ? s1 : s2);
    const int bn = bnG & (DD - 1);

#pragma unroll
    for (int mf = 0; mf < 4; ++mf) {
        const int row = bm + warp_m * 64 + mf * 16 + (lane >> 2);
#pragma unroll
        for (int nf = 0; nf < 4; ++nf) {
            const int col = bn + warp_n * 32 + nf * 8 + (lane & 3) * 2;
            const float b0 = bias ? bias[col] : 0.f;
            const float b1 = bias ? bias[col + 1] : 0.f;
            float2 v0, v1;
            v0.x = (acc[mf][nf][0] + b0) * scale;
            v0.y = (acc[mf][nf][1] + b1) * scale;
            v1.x = (acc[mf][nf][2] + b0) * scale;
            v1.y = (acc[mf][nf][3] + b1) * scale;
            *(float2*)(dst + (size_t)row * DD + col) = v0;
            *(float2*)(dst + (size_t)(row + 8) * DD + col) = v1;
        }
    }
}

// ---------------------------------------------------------------------------
// Causal flash attention via fp16 mma.sync.
// Block = 64 q-rows of one (b,h). 4 warps, warp w -> q rows 16w..16w+15.
// Q pre-scaled (fp32 in) -> fp16; K scaled on load; V transposed on load.
// P converted accumulator->A-fragment in registers (FA2 layout identity).
// ---------------------------------------------------------------------------
__global__ __launch_bounds__(128)
void attn_mma_kernel(const float* __restrict__ Q, const float* __restrict__ Kc,
                     const float* __restrict__ Vc, float* __restrict__ O)
{
    __shared__ __half Qs[64][AT_PAD];
    __shared__ __half Ks[64][AT_PAD];
    __shared__ __half Vts[64][AT_PAD];   // [dh][key]

    const int qt  = gridDim.x - 1 - blockIdx.x;   // heavy tiles launch first
    const int bh  = blockIdx.y;
    const int b   = bh >> 4;
    const int h   = bh & 15;
    const int tid = threadIdx.x;
    const int lane = tid & 31;
    const int w   = tid >> 5;
    const int q0  = qt * 64;
    const size_t base = (size_t)b * TT * DD + (size_t)h * DHH;

    // load Q tile (already scaled) -> fp16
    {
        const int r = tid >> 1, cs = (tid & 1) * 32;
        const float* src = Q + base + (size_t)(q0 + r) * DD + cs;
#pragma unroll
        for (int i = 0; i < 8; ++i) {
            float4 v = *(const float4*)(src + i * 4);
            Qs[r][cs + i * 4 + 0] = __float2half(v.x);
            Qs[r][cs + i * 4 + 1] = __float2half(v.y);
            Qs[r][cs + i * 4 + 2] = __float2half(v.z);
            Qs[r][cs + i * 4 + 3] = __float2half(v.w);
        }
    }
    __syncthreads();

    // preload Q A-fragments (persist across key tiles)
    uint32_t qf[4][4];
    {
        const int arow = w * 16 + (lane & 7) + ((lane >> 3) & 1) * 8;
        const int acol = (lane >> 4) * 8;
#pragma unroll
        for (int j = 0; j < 4; ++j)
            ldsm_x4(qf[j], smem_u32(&Qs[arow][acol + j * 16]));
    }

    float m0 = -1e30f, m1 = -1e30f, l0 = 0.f, l1 = 0.f;
    float oacc[8][4];
#pragma unroll
    for (int nf = 0; nf < 8; ++nf)
#pragma unroll
        for (int q = 0; q < 4; ++q) oacc[nf][q] = 0.f;

    const int brow = lane & 7;
    const int bcol = ((lane >> 3) & 1) * 8;

    for (int jt = 0; jt <= qt; ++jt) {
        const int k0 = jt * 64;
        // load K (scaled) and V (transposed)
        {
            const int r = tid >> 1, cs = (tid & 1) * 32;
            const float* ks = Kc + base + (size_t)(k0 + r) * DD + cs;
#pragma unroll
            for (int i = 0; i < 8; ++i) {
                float4 v = *(const float4*)(ks + i * 4);
                Ks[r][cs + i * 4 + 0] = __float2half(v.x * QK_SCALE);
                Ks[r][cs + i * 4 + 1] = __float2half(v.y * QK_SCALE);
                Ks[r][cs + i * 4 + 2] = __float2half(v.z * QK_SCALE);
                Ks[r][cs + i * 4 + 3] = __float2half(v.w * QK_SCALE);
            }
            const int vr = tid & 63, vc0 = (tid >> 6) * 32;
            const float* vs = Vc + base + (size_t)(k0 + vr) * DD + vc0;
#pragma unroll
            for (int i = 0; i < 8; ++i) {
                float4 v = *(const float4*)(vs + i * 4);
                Vts[vc0 + i * 4 + 0][vr] = __float2half(v.x);
                Vts[vc0 + i * 4 + 1][vr] = __float2half(v.y);
                Vts[vc0 + i * 4 + 2][vr] = __float2half(v.z);
                Vts[vc0 + i * 4 + 3][vr] = __float2half(v.w);
            }
        }
        __syncthreads();

        // S = Q K^T
        float sacc[8][4];
#pragma unroll
        for (int nf = 0; nf < 8; ++nf)
#pragma unroll
            for (int q = 0; q < 4; ++q) sacc[nf][q] = 0.f;

#pragma unroll
        for (int nf = 0; nf < 8; ++nf) {
            uint32_t kb[4][2];
#pragma unroll
            for (int j = 0; j < 4; ++j)
                ldsm_x2(kb[j], smem_u32(&Ks[nf * 8 + brow][j * 16 + bcol]));
#pragma unroll
            for (int j = 0; j < 4; ++j)
                mma16816h(sacc[nf], qf[j], kb[j]);
        }

        // causal mask on diagonal tile
        if (jt == qt) {
            const int ql0 = w * 16 + (lane >> 2);
#pragma unroll
            for (int nf = 0; nf < 8; ++nf) {
                const int kl = nf * 8 + (lane & 3) * 2;
                if (kl + 0 > ql0)     sacc[nf][0] += -1e9f;
                if (kl + 1 > ql0)     sacc[nf][1] += -1e9f;
                if (kl + 0 > ql0 + 8) sacc[nf][2] += -1e9f;
                if (kl + 1 > ql0 + 8) sacc[nf][3] += -1e9f;
            }
        }

        // online softmax (rows r0 = lane>>2, r1 = r0+8; quad-shared)
        float mn0 = m0, mn1 = m1;
#pragma unroll
        for (int nf = 0; nf < 8; ++nf) {
            mn0 = fmaxf(mn0, fmaxf(sacc[nf][0], sacc[nf][1]));
            mn1 = fmaxf(mn1, fmaxf(sacc[nf][2], sacc[nf][3]));
        }
        mn0 = fmaxf(mn0, __shfl_xor_sync(0xffffffffu, mn0, 1));
        mn0 = fmaxf(mn0, __shfl_xor_sync(0xffffffffu, mn0, 2));
        mn1 = fmaxf(mn1, __shfl_xor_sync(0xffffffffu, mn1, 1));
        mn1 = fmaxf(mn1, __shfl_xor_sync(0xffffffffu, mn1, 2));
        const float alpha0 = __expf(m0 - mn0);
        const float alpha1 = __expf(m1 - mn1);
        m0 = mn0; m1 = mn1;

        float rs0 = 0.f, rs1 = 0.f;
        uint32_t pa[4][4];
#pragma unroll
        for (int j = 0; j < 4; ++j) {
            // frag 2j -> a0 (rows r0, k 0..7), a1 (rows r1)
            {
                float p0 = __expf(sacc[2 * j][0] - m0);
                float p1 = __expf(sacc[2 * j][1] - m0);
                float p2 = __expf(sacc[2 * j][2] - m1);
                float p3 = __expf(sacc[2 * j][3] - m1);
                rs0 += p0 + p1; rs1 += p2 + p3;
                __half2 h01 = __floats2half2_rn(p0, p1);
                __half2 h23 = __floats2half2_rn(p2, p3);
                pa[j][0] = *(uint32_t*)&h01;
                pa[j][1] = *(uint32_t*)&h23;
            }
            // frag 2j+1 -> a2 (rows r0, k 8..15), a3 (rows r1)
            {
                float p0 = __expf(sacc[2 * j + 1][0] - m0);
                float p1 = __expf(sacc[2 * j + 1][1] - m0);
                float p2 = __expf(sacc[2 * j + 1][2] - m1);
                float p3 = __expf(sacc[2 * j + 1][3] - m1);
                rs0 += p0 + p1; rs1 += p2 + p3;
                __half2 h01 = __floats2half2_rn(p0, p1);
                __half2 h23 = __floats2half2_rn(p2, p3);
                pa[j][2] = *(uint32_t*)&h01;
                pa[j][3] = *(uint32_t*)&h23;
            }
        }
        l0 = l0 * alpha0 + rs0;
        l1 = l1 * alpha1 + rs1;

#pragma unroll
        for (int nf = 0; nf < 8; ++nf) {
            oacc[nf][0] *= alpha0; oacc[nf][1] *= alpha0;
            oacc[nf][2] *= alpha1; oacc[nf][3] *= alpha1;
        }

        // O += P @ V   (B-frags from transposed V: rows = dh, cols = key)
#pragma unroll
        for (int nf = 0; nf < 8; ++nf) {
            uint32_t vb[4][2];
#pragma unroll
            for (int j = 0; j < 4; ++j)
                ldsm_x2(vb[j], smem_u32(&Vts[nf * 8 + brow][j * 16 + bcol]));
#pragma unroll
            for (int j = 0; j < 4; ++j)
                mma16816h(oacc[nf], pa[j], vb[j]);
        }
        __syncthreads();   // done with Ks/Vts before next tile overwrite
    }

    // final row-sum reduce + normalize + store
    l0 += __shfl_xor_sync(0xffffffffu, l0, 1);
    l0 += __shfl_xor_sync(0xffffffffu, l0, 2);
    l1 += __shfl_xor_sync(0xffffffffu, l1, 1);
    l1 += __shfl_xor_sync(0xffffffffu, l1, 2);
    const float inv0 = 1.0f / l0;
    const float inv1 = 1.0f / l1;

    const int r0 = q0 + w * 16 + (lane >> 2);
#pragma unroll
    for (int nf = 0; nf < 8; ++nf) {
        const int col = nf * 8 + (lane & 3) * 2;
        float2 v0, v1;
        v0.x = oacc[nf][0] * inv0; v0.y = oacc[nf][1] * inv0;
        v1.x = oacc[nf][2] * inv1; v1.y = oacc[nf][3] * inv1;
        *(float2*)(O + base + (size_t)r0 * DD + col) = v0;
        *(float2*)(O + base + (size_t)(r0 + 8) * DD + col) = v1;
    }
}

// ---------------------------------------------------------------------------
// Launch
// Inputs: x, k_cache, v_cache, mask, Wq, bq, Wk, Wv, bv, Wo, bo
// Output: [out | k_cache | v_cache]
// ---------------------------------------------------------------------------
extern "C" void kernel_launch(void* const* d_in, const int* in_sizes, int n_in,
                              void* d_out, int out_size)
{
    (void)in_sizes; (void)n_in;
    const float* x  = (const float*)d_in[0];
    const float* Wq = (const float*)d_in[4];
    const float* bq = (const float*)d_in[5];
    const float* Wk = (const float*)d_in[6];
    const float* Wv = (const float*)d_in[7];
    const float* bv = (const float*)d_in[8];
    const float* Wo = (const float*)d_in[9];
    const float* bo = (const float*)d_in[10];
    float* out = (float*)d_out;

    float *qp, *ap, *kfp, *vfp;
    __nv_bfloat16 *shi, *slo, *whi, *wlo;
    cudaGetSymbolAddress((void**)&qp,  g_q);
    cudaGetSymbolAddress((void**)&ap,  g_attn);
    cudaGetSymbolAddress((void**)&kfp, g_kfall);
    cudaGetSymbolAddress((void**)&vfp, g_vfall);
    cudaGetSymbolAddress((void**)&shi, g_split_hi);
    cudaGetSymbolAddress((void**)&slo, g_split_lo);
    cudaGetSymbolAddress((void**)&whi, g_wt_hi);
    cudaGetSymbolAddress((void**)&wlo, g_wt_lo);

    const size_t btd = (size_t)BT * DD;
    const size_t wsz = (size_t)DD * DD;
    float* kdst = kfp;
    float* vdst = vfp;
    if ((size_t)out_size >= 3 * btd) {
        kdst = out + btd;
        vdst = out + 2 * btd;
    }

    // 1. all 4 weight transposes + splits in one launch
    wconv4_kernel<<<dim3(32, 32, 4), 256>>>(Wq, Wk, Wv, Wo, whi, wlo);

    // 2. split x
    split_kernel<<<(int)(btd / 1024), 256>>>(x, shi, slo);

    // 3. fused QKV projection (N = 3072)
    cudaFuncSetAttribute(gemm_mma_kernel, cudaFuncAttributeMaxDynamicSharedMemorySize, GEMM_SMEM);
    gemm_mma_kernel<<<dim3(3 * DD / BN, BT / BM), 256, GEMM_SMEM>>>(
        shi, slo, whi, wlo,
        qp, kdst, vdst, bq, nullptr, bv, QK_SCALE, 1.0f, 1.0f);

    // 4. attention (fp16 tensor cores)
    attn_mma_kernel<<<dim3(TT / 64, BB * HH), 128>>>(qp, kdst, vdst, ap);

    // 5. split attn output, 6. output projection
    split_kernel<<<(int)(btd / 1024), 256>>>(ap, shi, slo);
    gemm_mma_kernel<<<dim3(DD / BN, BT / BM), 256, GEMM_SMEM>>>(
        shi, slo, whi + 3 * wsz, wlo + 3 * wsz,
        out, out, out, bo, bo, bo, 1.0f, 1.0f, 1.0f);
}

// round 5
// speedup vs baseline: 2.8494x; 1.0903x over previous
#include <cuda_runtime.h>
#include <cuda_bf16.h>
#include <cuda_fp16.h>
#include <cstdint>
#include <cstddef>

// Problem constants
#define BB   8
#define TT   448
#define DD   1024
#define HH   16
#define DHH  64
#define BT   (BB * TT)              // 3584
#define QK_SCALE 0.35355339059327373f   // 64^(-0.25)

// GEMM tiling (mma.sync path)
#define BM 128
#define BN 128
#define BK 32
#define NCHUNKS (DD / BK)           // 32
#define PADE 40                     // padded row stride in bf16 elems
#define MAT_BYTES (128 * PADE * 2)  // 10240 per matrix tile
#define STG_BYTES (4 * MAT_BYTES)   // 40960 per stage
#define GEMM_SMEM (2 * STG_BYTES)   // 81920

#define AT_PAD 72                   // attn smem row stride (halves); 144B, 16B-aligned

// Scratch (allocation-free rule: __device__ globals)
__device__ float g_kfall[(size_t)BT * DD];
__device__ float g_vfall[(size_t)BT * DD];
__device__ __half g_qh[(size_t)BT * DD];                // q * QK_SCALE, fp16
__device__ __half g_kh[(size_t)BT * DD];                // k * QK_SCALE, fp16
__device__ __half g_vh[(size_t)BT * DD];                // v, fp16
__device__ __nv_bfloat16 g_split_hi[(size_t)BT * DD];
__device__ __nv_bfloat16 g_split_lo[(size_t)BT * DD];
__device__ __nv_bfloat16 g_wt_hi[4][(size_t)DD * DD];   // W^T hi, [n][k]
__device__ __nv_bfloat16 g_wt_lo[4][(size_t)DD * DD];

// ---------------------------------------------------------------------------
// PTX helpers (plain sm_80+ ISA)
// ---------------------------------------------------------------------------
__device__ __forceinline__ uint32_t smem_u32(const void* p) {
    uint32_t a;
    asm("{ .reg .u64 t; cvta.to.shared.u64 t, %1; cvt.u32.u64 %0, t; }" : "=r"(a) : "l"(p));
    return a;
}
__device__ __forceinline__ void cpasync16(uint32_t dst, const void* src) {
    asm volatile("cp.async.cg.shared.global [%0], [%1], 16;" :: "r"(dst), "l"(src));
}
#define CP_COMMIT() asm volatile("cp.async.commit_group;" ::: "memory")
#define CP_WAIT0()  asm volatile("cp.async.wait_group 0;" ::: "memory")

__device__ __forceinline__ void ldsm_x4(uint32_t* r, uint32_t a) {
    asm volatile("ldmatrix.sync.aligned.m8n8.x4.shared.b16 {%0,%1,%2,%3}, [%4];"
        : "=r"(r[0]), "=r"(r[1]), "=r"(r[2]), "=r"(r[3]) : "r"(a));
}
__device__ __forceinline__ void ldsm_x2(uint32_t* r, uint32_t a) {
    asm volatile("ldmatrix.sync.aligned.m8n8.x2.shared.b16 {%0,%1}, [%2];"
        : "=r"(r[0]), "=r"(r[1]) : "r"(a));
}
__device__ __forceinline__ void ldsm_x2t(uint32_t* r, uint32_t a) {
    asm volatile("ldmatrix.sync.aligned.m8n8.x2.trans.shared.b16 {%0,%1}, [%2];"
        : "=r"(r[0]), "=r"(r[1]) : "r"(a));
}
__device__ __forceinline__ void mma16816(float* d, const uint32_t* a, const uint32_t* b) {
    asm volatile("mma.sync.aligned.m16n8k16.row.col.f32.bf16.bf16.f32 "
        "{%0,%1,%2,%3}, {%4,%5,%6,%7}, {%8,%9}, {%0,%1,%2,%3};"
        : "+f"(d[0]), "+f"(d[1]), "+f"(d[2]), "+f"(d[3])
        : "r"(a[0]), "r"(a[1]), "r"(a[2]), "r"(a[3]), "r"(b[0]), "r"(b[1]));
}
__device__ __forceinline__ void mma16816h(float* d, const uint32_t* a, const uint32_t* b) {
    asm volatile("mma.sync.aligned.m16n8k16.row.col.f32.f16.f16.f32 "
        "{%0,%1,%2,%3}, {%4,%5,%6,%7}, {%8,%9}, {%0,%1,%2,%3};"
        : "+f"(d[0]), "+f"(d[1]), "+f"(d[2]), "+f"(d[3])
        : "r"(a[0]), "r"(a[1]), "r"(a[2]), "r"(a[3]), "r"(b[0]), "r"(b[1]));
}

// ---------------------------------------------------------------------------
// fp32 -> bf16 hi/lo split (elementwise), used for x only
// ---------------------------------------------------------------------------
__global__ __launch_bounds__(256)
void split_kernel(const float* __restrict__ in,
                  __nv_bfloat16* __restrict__ hi, __nv_bfloat16* __restrict__ lo)
{
    const size_t i = ((size_t)blockIdx.x * 256 + threadIdx.x) * 4;
    float4 v = *(const float4*)(in + i);
    __nv_bfloat162 h01, h23, l01, l23;
    h01.x = __float2bfloat16(v.x); h01.y = __float2bfloat16(v.y);
    h23.x = __float2bfloat16(v.z); h23.y = __float2bfloat16(v.w);
    l01.x = __float2bfloat16(v.x - __bfloat162float(h01.x));
    l01.y = __float2bfloat16(v.y - __bfloat162float(h01.y));
    l23.x = __float2bfloat16(v.z - __bfloat162float(h23.x));
    l23.y = __float2bfloat16(v.w - __bfloat162float(h23.y));
    uint2 hp, lp;
    hp.x = *(uint32_t*)&h01; hp.y = *(uint32_t*)&h23;
    lp.x = *(uint32_t*)&l01; lp.y = *(uint32_t*)&l23;
    *(uint2*)(hi + i) = hp;
    *(uint2*)(lo + i) = lp;
}

// ---------------------------------------------------------------------------
// Weight transpose + bf16 hi/lo split, all 4 matrices in one launch (z dim)
// ---------------------------------------------------------------------------
__global__ __launch_bounds__(256)
void wconv4_kernel(const float* __restrict__ W0, const float* __restrict__ W1,
                   const float* __restrict__ W2, const float* __restrict__ W3,
                   __nv_bfloat16* __restrict__ hiB, __nv_bfloat16* __restrict__ loB)
{
    __shared__ float t[32][33];
    const int z = blockIdx.z;
    const float* W = (z == 0) ? W0 : (z == 1) ? W1 : (z == 2) ? W2 : W3;
    __nv_bfloat16* hi = hiB + (size_t)z * DD * DD;
    __nv_bfloat16* lo = loB + (size_t)z * DD * DD;
    const int k0 = blockIdx.y * 32, n0 = blockIdx.x * 32;
    const int tx = threadIdx.x & 31, ty = threadIdx.x >> 5;
#pragma unroll
    for (int i = 0; i < 4; ++i)
        t[ty + i * 8][tx] = W[(size_t)(k0 + ty + i * 8) * DD + n0 + tx];
    __syncthreads();
#pragma unroll
    for (int i = 0; i < 4; ++i) {
        const int n = n0 + ty + i * 8, k = k0 + tx;
        float v = t[tx][ty + i * 8];
        __nv_bfloat16 h = __float2bfloat16(v);
        __nv_bfloat16 l = __float2bfloat16(v - __bfloat162float(h));
        hi[(size_t)n * DD + k] = h;
        lo[(size_t)n * DD + k] = l;
    }
}

// ---------------------------------------------------------------------------
// 3xBF16-split GEMM via mma.sync. Epilogue can emit fp32 (+bias,*scale) and/or
// an fp16 copy scaled by hscale (for attention inputs).
// ---------------------------------------------------------------------------
__global__ __launch_bounds__(256)
void gemm_mma_kernel(const __nv_bfloat16* __restrict__ Ahi,
                     const __nv_bfloat16* __restrict__ Alo,
                     const __nv_bfloat16* __restrict__ Bhi,
                     const __nv_bfloat16* __restrict__ Blo,
                     float* __restrict__ d0, float* __restrict__ d1, float* __restrict__ d2,
                     __half* __restrict__ h0, __half* __restrict__ h1, __half* __restrict__ h2,
                     const float* __restrict__ bias0, const float* __restrict__ bias1,
                     const float* __restrict__ bias2,
                     float hs0, float hs1, float hs2)
{
    extern __shared__ char smem[];
    const uint32_t sb = smem_u32(smem);
    const int tid  = threadIdx.x;
    const int lane = tid & 31;
    const int wid  = tid >> 5;
    const int warp_m = wid >> 2;
    const int warp_n = wid & 3;
    const int bm  = blockIdx.y * BM;
    const int bnG = blockIdx.x * BN;

    float acc[4][4][4];
#pragma unroll
    for (int i = 0; i < 4; ++i)
#pragma unroll
        for (int j = 0; j < 4; ++j)
#pragma unroll
            for (int q = 0; q < 4; ++q) acc[i][j][q] = 0.f;

    const int lrow = tid >> 2;
    const int lseg = (tid & 3) * 8;
    const __nv_bfloat16* srcA0 = Ahi + (size_t)bm  * DD + lseg;
    const __nv_bfloat16* srcA1 = Alo + (size_t)bm  * DD + lseg;
    const __nv_bfloat16* srcB0 = Bhi + (size_t)bnG * DD + lseg;
    const __nv_bfloat16* srcB1 = Blo + (size_t)bnG * DD + lseg;

    auto load_chunk = [&](int c, int s) {
        const int k0 = c * BK;
        const uint32_t dbase = sb + s * STG_BYTES;
#pragma unroll
        for (int i = 0; i < 2; ++i) {
            const int row = lrow + i * 64;
            const size_t goff = (size_t)row * DD + k0;
            const uint32_t soff = (uint32_t)(row * PADE + lseg) * 2;
            cpasync16(dbase + 0 * MAT_BYTES + soff, srcA0 + goff);
            cpasync16(dbase + 1 * MAT_BYTES + soff, srcA1 + goff);
            cpasync16(dbase + 2 * MAT_BYTES + soff, srcB0 + goff);
            cpasync16(dbase + 3 * MAT_BYTES + soff, srcB1 + goff);
        }
    };

    const int arow = warp_m * 64 + (lane & 7) + ((lane >> 3) & 1) * 8;
    const int acol = (lane >> 4) * 8;
    const int brow = warp_n * 32 + (lane & 7);
    const int bcol = ((lane >> 3) & 1) * 8;

    load_chunk(0, 0);
    CP_COMMIT();

    for (int c = 0; c < NCHUNKS; ++c) {
        CP_WAIT0();
        __syncthreads();
        if (c + 1 < NCHUNKS) {
            load_chunk(c + 1, (c + 1) & 1);
            CP_COMMIT();
        }
        const uint32_t st = sb + (c & 1) * STG_BYTES;

#pragma unroll
        for (int k16 = 0; k16 < BK; k16 += 16) {
            uint32_t bh[4][2], bl[4][2];
#pragma unroll
            for (int nf = 0; nf < 4; ++nf) {
                const uint32_t bo = (uint32_t)((brow + nf * 8) * PADE + bcol + k16) * 2;
                ldsm_x2(bh[nf], st + 2 * MAT_BYTES + bo);
                ldsm_x2(bl[nf], st + 3 * MAT_BYTES + bo);
            }
#pragma unroll
            for (int mf = 0; mf < 4; ++mf) {
                uint32_t ah[4], al[4];
                const uint32_t ao = (uint32_t)((arow + mf * 16) * PADE + acol + k16) * 2;
                ldsm_x4(ah, st + 0 * MAT_BYTES + ao);
                ldsm_x4(al, st + 1 * MAT_BYTES + ao);
#pragma unroll
                for (int nf = 0; nf < 4; ++nf) {
                    mma16816(acc[mf][nf], ah, bh[nf]);
                    mma16816(acc[mf][nf], ah, bl[nf]);
                    mma16816(acc[mf][nf], al, bh[nf]);
                }
            }
        }
    }

    const int mat = bnG >> 10;
    float* dst = (mat == 0) ? d0 : ((mat == 1) ? d1 : d2);
    __half* hdst = (mat == 0) ? h0 : ((mat == 1) ? h1 : h2);
    const float* bias = (mat == 0) ? bias0 : ((mat == 1) ? bias1 : bias2);
    const float hscale = (mat == 0) ? hs0 : ((mat == 1) ? hs1 : hs2);
    const int bn = bnG & (DD - 1);

#pragma unroll
    for (int mf = 0; mf < 4; ++mf) {
        const int row = bm + warp_m * 64 + mf * 16 + (lane >> 2);
#pragma unroll
        for (int nf = 0; nf < 4; ++nf) {
            const int col = bn + warp_n * 32 + nf * 8 + (lane & 3) * 2;
            const float b0 = bias ? bias[col] : 0.f;
            const float b1 = bias ? bias[col + 1] : 0.f;
            const float v00 = acc[mf][nf][0] + b0;
            const float v01 = acc[mf][nf][1] + b1;
            const float v10 = acc[mf][nf][2] + b0;
            const float v11 = acc[mf][nf][3] + b1;
            if (dst) {
                *(float2*)(dst + (size_t)row * DD + col) = make_float2(v00, v01);
                *(float2*)(dst + (size_t)(row + 8) * DD + col) = make_float2(v10, v11);
            }
            if (hdst) {
                __half2 q0 = __floats2half2_rn(v00 * hscale, v01 * hscale);
                __half2 q1 = __floats2half2_rn(v10 * hscale, v11 * hscale);
                *(__half2*)(hdst + (size_t)row * DD + col) = q0;
                *(__half2*)(hdst + (size_t)(row + 8) * DD + col) = q1;
            }
        }
    }
}

// ---------------------------------------------------------------------------
// Causal flash attention, fp16 mma.sync, fp16 inputs, cp.async double buffer.
// Block = 64 q-rows of one (b,h), 4 warps. V loaded row-major, B-frags via
// ldmatrix.trans. Output written as bf16 hi/lo splits (feeds out-projection).
// ---------------------------------------------------------------------------
__global__ __launch_bounds__(128)
void attn_mma_kernel(const __half* __restrict__ Qh, const __half* __restrict__ Kh,
                     const __half* __restrict__ Vh,
                     __nv_bfloat16* __restrict__ OutHi, __nv_bfloat16* __restrict__ OutLo)
{
    __shared__ __half Qs[64][AT_PAD];
    __shared__ __half Ks[2][64][AT_PAD];
    __shared__ __half Vs[2][64][AT_PAD];

    const int qt  = gridDim.x - 1 - blockIdx.x;   // heavy tiles launch first
    const int bh  = blockIdx.y;
    const int b   = bh >> 4;
    const int h   = bh & 15;
    const int tid = threadIdx.x;
    const int lane = tid & 31;
    const int w   = tid >> 5;
    const int q0  = qt * 64;
    const size_t base = (size_t)b * TT * DD + (size_t)h * DHH;

    // K/V tile loader: 64 rows x 64 halves = 512 x 16B, 4 segs/thread each
    auto load_kv = [&](int jt, int s) {
        const int k0 = jt * 64;
#pragma unroll
        for (int i = 0; i < 4; ++i) {
            const int seg = tid * 4 + i;
            const int row = seg >> 3;
            const int c8  = (seg & 7) * 8;
            const size_t goff = base + (size_t)(k0 + row) * DD + c8;
            cpasync16(smem_u32(&Ks[s][row][c8]), Kh + goff);
            cpasync16(smem_u32(&Vs[s][row][c8]), Vh + goff);
        }
    };

    // Q tile: plain loads (once)
#pragma unroll
    for (int i = 0; i < 4; ++i) {
        const int seg = tid * 4 + i;
        const int row = seg >> 3;
        const int c8  = (seg & 7) * 8;
        *(uint4*)&Qs[row][c8] = *(const uint4*)(Qh + base + (size_t)(q0 + row) * DD + c8);
    }

    load_kv(0, 0);
    CP_COMMIT();
    __syncthreads();   // Qs visible

    // Q A-fragments (persist)
    uint32_t qf[4][4];
    {
        const int arow = w * 16 + (lane & 7) + ((lane >> 3) & 1) * 8;
        const int acol = (lane >> 4) * 8;
#pragma unroll
        for (int j = 0; j < 4; ++j)
            ldsm_x4(qf[j], smem_u32(&Qs[arow][acol + j * 16]));
    }

    float m0 = -1e30f, m1 = -1e30f, l0 = 0.f, l1 = 0.f;
    float oacc[8][4];
#pragma unroll
    for (int nf = 0; nf < 8; ++nf)
#pragma unroll
        for (int q = 0; q < 4; ++q) oacc[nf][q] = 0.f;

    const int brow = lane & 7;
    const int bcol = ((lane >> 3) & 1) * 8;
    const int vrow = lane & 15;

    for (int jt = 0; jt <= qt; ++jt) {
        const int s = jt & 1;
        CP_WAIT0();
        __syncthreads();           // stage s ready; prior compute on s^1 done
        if (jt + 1 <= qt) {
            load_kv(jt + 1, s ^ 1);
            CP_COMMIT();
        }

        // S = Q K^T
        float sacc[8][4];
#pragma unroll
        for (int nf = 0; nf < 8; ++nf)
#pragma unroll
            for (int q = 0; q < 4; ++q) sacc[nf][q] = 0.f;

#pragma unroll
        for (int nf = 0; nf < 8; ++nf) {
            uint32_t kb[4][2];
#pragma unroll
            for (int j = 0; j < 4; ++j)
                ldsm_x2(kb[j], smem_u32(&Ks[s][nf * 8 + brow][j * 16 + bcol]));
#pragma unroll
            for (int j = 0; j < 4; ++j)
                mma16816h(sacc[nf], qf[j], kb[j]);
        }

        // causal mask on diagonal tile
        if (jt == qt) {
            const int ql0 = w * 16 + (lane >> 2);
#pragma unroll
            for (int nf = 0; nf < 8; ++nf) {
                const int kl = nf * 8 + (lane & 3) * 2;
                if (kl + 0 > ql0)     sacc[nf][0] += -1e9f;
                if (kl + 1 > ql0)     sacc[nf][1] += -1e9f;
                if (kl + 0 > ql0 + 8) sacc[nf][2] += -1e9f;
                if (kl + 1 > ql0 + 8) sacc[nf][3] += -1e9f;
            }
        }

        // online softmax (rows r0 = lane>>2, r1 = r0+8; quad-shared)
        float mn0 = m0, mn1 = m1;
#pragma unroll
        for (int nf = 0; nf < 8; ++nf) {
            mn0 = fmaxf(mn0, fmaxf(sacc[nf][0], sacc[nf][1]));
            mn1 = fmaxf(mn1, fmaxf(sacc[nf][2], sacc[nf][3]));
        }
        mn0 = fmaxf(mn0, __shfl_xor_sync(0xffffffffu, mn0, 1));
        mn0 = fmaxf(mn0, __shfl_xor_sync(0xffffffffu, mn0, 2));
        mn1 = fmaxf(mn1, __shfl_xor_sync(0xffffffffu, mn1, 1));
        mn1 = fmaxf(mn1, __shfl_xor_sync(0xffffffffu, mn1, 2));
        const float alpha0 = __expf(m0 - mn0);
        const float alpha1 = __expf(m1 - mn1);
        m0 = mn0; m1 = mn1;

        float rs0 = 0.f, rs1 = 0.f;
        uint32_t pa[4][4];
#pragma unroll
        for (int j = 0; j < 4; ++j) {
            {
                float p0 = __expf(sacc[2 * j][0] - m0);
                float p1 = __expf(sacc[2 * j][1] - m0);
                float p2 = __expf(sacc[2 * j][2] - m1);
                float p3 = __expf(sacc[2 * j][3] - m1);
                rs0 += p0 + p1; rs1 += p2 + p3;
                __half2 h01 = __floats2half2_rn(p0, p1);
                __half2 h23 = __floats2half2_rn(p2, p3);
                pa[j][0] = *(uint32_t*)&h01;
                pa[j][1] = *(uint32_t*)&h23;
            }
            {
                float p0 = __expf(sacc[2 * j + 1][0] - m0);
                float p1 = __expf(sacc[2 * j + 1][1] - m0);
                float p2 = __expf(sacc[2 * j + 1][2] - m1);
                float p3 = __expf(sacc[2 * j + 1][3] - m1);
                rs0 += p0 + p1; rs1 += p2 + p3;
                __half2 h01 = __floats2half2_rn(p0, p1);
                __half2 h23 = __floats2half2_rn(p2, p3);
                pa[j][2] = *(uint32_t*)&h01;
                pa[j][3] = *(uint32_t*)&h23;
            }
        }
        l0 = l0 * alpha0 + rs0;
        l1 = l1 * alpha1 + rs1;

#pragma unroll
        for (int nf = 0; nf < 8; ++nf) {
            oacc[nf][0] *= alpha0; oacc[nf][1] *= alpha0;
            oacc[nf][2] *= alpha1; oacc[nf][3] *= alpha1;
        }

        // O += P @ V  (B-frags via ldmatrix.trans from row-major V)
#pragma unroll
        for (int nf = 0; nf < 8; ++nf) {
            uint32_t vb[4][2];
#pragma unroll
            for (int j = 0; j < 4; ++j)
                ldsm_x2t(vb[j], smem_u32(&Vs[s][j * 16 + vrow][nf * 8]));
#pragma unroll
            for (int j = 0; j < 4; ++j)
                mma16816h(oacc[nf], pa[j], vb[j]);
        }
        __syncthreads();   // done with stage s before it is refilled
    }

    // final row-sum reduce + normalize + bf16 hi/lo store
    l0 += __shfl_xor_sync(0xffffffffu, l0, 1);
    l0 += __shfl_xor_sync(0xffffffffu, l0, 2);
    l1 += __shfl_xor_sync(0xffffffffu, l1, 1);
    l1 += __shfl_xor_sync(0xffffffffu, l1, 2);
    const float inv0 = 1.0f / l0;
    const float inv1 = 1.0f / l1;

    const int r0 = q0 + w * 16 + (lane >> 2);
#pragma unroll
    for (int nf = 0; nf < 8; ++nf) {
        const int col = nf * 8 + (lane & 3) * 2;
        const float x00 = oacc[nf][0] * inv0, x01 = oacc[nf][1] * inv0;
        const float x10 = oacc[nf][2] * inv1, x11 = oacc[nf][3] * inv1;
        __nv_bfloat162 h0, l0v, h1, l1v;
        h0.x = __float2bfloat16(x00); h0.y = __float2bfloat16(x01);
        l0v.x = __float2bfloat16(x00 - __bfloat162float(h0.x));
        l0v.y = __float2bfloat16(x01 - __bfloat162float(h0.y));
        h1.x = __float2bfloat16(x10); h1.y = __float2bfloat16(x11);
        l1v.x = __float2bfloat16(x10 - __bfloat162float(h1.x));
        l1v.y = __float2bfloat16(x11 - __bfloat162float(h1.y));
        const size_t o0 = base + (size_t)r0 * DD + col;
        const size_t o1 = base + (size_t)(r0 + 8) * DD + col;
        *(__nv_bfloat162*)(OutHi + o0) = h0;
        *(__nv_bfloat162*)(OutLo + o0) = l0v;
        *(__nv_bfloat162*)(OutHi + o1) = h1;
        *(__nv_bfloat162*)(OutLo + o1) = l1v;
    }
}

// ---------------------------------------------------------------------------
// Launch
// Inputs: x, k_cache, v_cache, mask, Wq, bq, Wk, Wv, bv, Wo, bo
// Output: [out | k_cache | v_cache]
// ---------------------------------------------------------------------------
extern "C" void kernel_launch(void* const* d_in, const int* in_sizes, int n_in,
                              void* d_out, int out_size)
{
    (void)in_sizes; (void)n_in;
    const float* x  = (const float*)d_in[0];
    const float* Wq = (const float*)d_in[4];
    const float* bq = (const float*)d_in[5];
    const float* Wk = (const float*)d_in[6];
    const float* Wv = (const float*)d_in[7];
    const float* bv = (const float*)d_in[8];
    const float* Wo = (const float*)d_in[9];
    const float* bo = (const float*)d_in[10];
    float* out = (float*)d_out;

    float *kfp, *vfp;
    __half *qh, *kh, *vh;
    __nv_bfloat16 *shi, *slo, *whi, *wlo;
    cudaGetSymbolAddress((void**)&kfp, g_kfall);
    cudaGetSymbolAddress((void**)&vfp, g_vfall);
    cudaGetSymbolAddress((void**)&qh,  g_qh);
    cudaGetSymbolAddress((void**)&kh,  g_kh);
    cudaGetSymbolAddress((void**)&vh,  g_vh);
    cudaGetSymbolAddress((void**)&shi, g_split_hi);
    cudaGetSymbolAddress((void**)&slo, g_split_lo);
    cudaGetSymbolAddress((void**)&whi, g_wt_hi);
    cudaGetSymbolAddress((void**)&wlo, g_wt_lo);

    const size_t btd = (size_t)BT * DD;
    const size_t wsz = (size_t)DD * DD;
    float* kdst = kfp;
    float* vdst = vfp;
    if ((size_t)out_size >= 3 * btd) {
        kdst = out + btd;
        vdst = out + 2 * btd;
    }

    // 1. weight transposes + splits (one launch)
    wconv4_kernel<<<dim3(32, 32, 4), 256>>>(Wq, Wk, Wv, Wo, whi, wlo);

    // 2. split x
    split_kernel<<<(int)(btd / 1024), 256>>>(x, shi, slo);

    // 3. fused QKV projection (N = 3072):
    //    mat0: q -> fp16 only (scaled); mat1: k -> fp32 + fp16(scaled); mat2: v -> fp32 + fp16
    cudaFuncSetAttribute(gemm_mma_kernel, cudaFuncAttributeMaxDynamicSharedMemorySize, GEMM_SMEM);
    gemm_mma_kernel<<<dim3(3 * DD / BN, BT / BM), 256, GEMM_SMEM>>>(
        shi, slo, whi, wlo,
        nullptr, kdst, vdst,
        qh, kh, vh,
        bq, nullptr, bv,
        QK_SCALE, QK_SCALE, 1.0f);

    // 4. attention (fp16 in, bf16 hi/lo out)
    attn_mma_kernel<<<dim3(TT / 64, BB * HH), 128>>>(qh, kh, vh, shi, slo);

    // 5. output projection (fp32 out only)
    gemm_mma_kernel<<<dim3(DD / BN, BT / BM), 256, GEMM_SMEM>>>(
        shi, slo, whi + 3 * wsz, wlo + 3 * wsz,
        out, out, out,
        nullptr, nullptr, nullptr,
        bo, bo, bo,
        1.0f, 1.0f, 1.0f);
}

// round 6
// speedup vs baseline: 3.5978x; 1.2626x over previous
#include <cuda_runtime.h>
#include <cuda_fp16.h>
#include <cstdint>
#include <cstddef>

// Problem constants
#define BB   8
#define TT   448
#define DD   1024
#define HH   16
#define DHH  64
#define BT   (BB * TT)              // 3584
#define QK_SCALE 0.35355339059327373f   // 64^(-0.25)

// GEMM tiling (mma.sync path)
#define BM 128
#define BN 128
#define BK 32
#define NCHUNKS (DD / BK)           // 32
#define PADE 40                     // padded row stride in halves
#define MAT_BYTES (128 * PADE * 2)  // 10240 per matrix tile
#define STG_BYTES (3 * MAT_BYTES)   // 30720 per stage (A, Bhi, Blo)
#define GEMM_SMEM (2 * STG_BYTES)   // 61440

#define AT_PAD 72                   // attn smem row stride (halves)

// Scratch (allocation-free rule: __device__ globals)
__device__ float  g_kfall[(size_t)BT * DD];
__device__ float  g_vfall[(size_t)BT * DD];
__device__ __half g_xh[(size_t)BT * DD];        // x, fp16
__device__ __half g_ah[(size_t)BT * DD];        // attn out, fp16
__device__ __half g_qh[(size_t)BT * DD];        // q * QK_SCALE, fp16
__device__ __half g_kh[(size_t)BT * DD];        // k * QK_SCALE, fp16
__device__ __half g_vh[(size_t)BT * DD];        // v, fp16
__device__ __half g_wt_hi[4][(size_t)DD * DD];  // W^T hi, [n][k], fp16
__device__ __half g_wt_lo[4][(size_t)DD * DD];  // W^T lo, fp16

// ---------------------------------------------------------------------------
// PTX helpers (plain sm_80+ ISA)
// ---------------------------------------------------------------------------
__device__ __forceinline__ uint32_t smem_u32(const void* p) {
    uint32_t a;
    asm("{ .reg .u64 t; cvta.to.shared.u64 t, %1; cvt.u32.u64 %0, t; }" : "=r"(a) : "l"(p));
    return a;
}
__device__ __forceinline__ void cpasync16(uint32_t dst, const void* src) {
    asm volatile("cp.async.cg.shared.global [%0], [%1], 16;" :: "r"(dst), "l"(src));
}
#define CP_COMMIT() asm volatile("cp.async.commit_group;" ::: "memory")
#define CP_WAIT0()  asm volatile("cp.async.wait_group 0;" ::: "memory")

__device__ __forceinline__ void ldsm_x4(uint32_t* r, uint32_t a) {
    asm volatile("ldmatrix.sync.aligned.m8n8.x4.shared.b16 {%0,%1,%2,%3}, [%4];"
        : "=r"(r[0]), "=r"(r[1]), "=r"(r[2]), "=r"(r[3]) : "r"(a));
}
__device__ __forceinline__ void ldsm_x2(uint32_t* r, uint32_t a) {
    asm volatile("ldmatrix.sync.aligned.m8n8.x2.shared.b16 {%0,%1}, [%2];"
        : "=r"(r[0]), "=r"(r[1]) : "r"(a));
}
__device__ __forceinline__ void ldsm_x2t(uint32_t* r, uint32_t a) {
    asm volatile("ldmatrix.sync.aligned.m8n8.x2.trans.shared.b16 {%0,%1}, [%2];"
        : "=r"(r[0]), "=r"(r[1]) : "r"(a));
}
__device__ __forceinline__ void mma16816h(float* d, const uint32_t* a, const uint32_t* b) {
    asm volatile("mma.sync.aligned.m16n8k16.row.col.f32.f16.f16.f32 "
        "{%0,%1,%2,%3}, {%4,%5,%6,%7}, {%8,%9}, {%0,%1,%2,%3};"
        : "+f"(d[0]), "+f"(d[1]), "+f"(d[2]), "+f"(d[3])
        : "r"(a[0]), "r"(a[1]), "r"(a[2]), "r"(a[3]), "r"(b[0]), "r"(b[1]));
}

// ---------------------------------------------------------------------------
// fp32 -> fp16 convert (elementwise), 4 floats/thread
// ---------------------------------------------------------------------------
__global__ __launch_bounds__(256)
void tohalf_kernel(const float* __restrict__ in, __half* __restrict__ outp)
{
    const size_t i = ((size_t)blockIdx.x * 256 + threadIdx.x) * 4;
    float4 v = *(const float4*)(in + i);
    __half2 a = __floats2half2_rn(v.x, v.y);
    __half2 b = __floats2half2_rn(v.z, v.w);
    uint2 p;
    p.x = *(uint32_t*)&a; p.y = *(uint32_t*)&b;
    *(uint2*)(outp + i) = p;
}

// ---------------------------------------------------------------------------
// Weight transpose + fp16 hi/lo split, all 4 matrices in one launch (z dim)
// ---------------------------------------------------------------------------
__global__ __launch_bounds__(256)
void wconv4_kernel(const float* __restrict__ W0, const float* __restrict__ W1,
                   const float* __restrict__ W2, const float* __restrict__ W3,
                   __half* __restrict__ hiB, __half* __restrict__ loB)
{
    __shared__ float t[32][33];
    const int z = blockIdx.z;
    const float* W = (z == 0) ? W0 : (z == 1) ? W1 : (z == 2) ? W2 : W3;
    __half* hi = hiB + (size_t)z * DD * DD;
    __half* lo = loB + (size_t)z * DD * DD;
    const int k0 = blockIdx.y * 32, n0 = blockIdx.x * 32;
    const int tx = threadIdx.x & 31, ty = threadIdx.x >> 5;
#pragma unroll
    for (int i = 0; i < 4; ++i)
        t[ty + i * 8][tx] = W[(size_t)(k0 + ty + i * 8) * DD + n0 + tx];
    __syncthreads();
#pragma unroll
    for (int i = 0; i < 4; ++i) {
        const int n = n0 + ty + i * 8, k = k0 + tx;
        float v = t[tx][ty + i * 8];
        __half h = __float2half(v);
        __half l = __float2half(v - __half2float(h));
        hi[(size_t)n * DD + k] = h;
        lo[(size_t)n * DD + k] = l;
    }
}

// ---------------------------------------------------------------------------
// 2-term fp16-split GEMM via mma.sync:
//   C = A(fp16) @ (Whi + Wlo)^T   (+bias), fp32 accum.
// Epilogue emits fp32 (+bias) and/or fp16 (*hscale) copies.
// CTA 128x128, BK=32, 256 threads (8 warps 2x4), cp.async double buffer.
// ---------------------------------------------------------------------------
__global__ __launch_bounds__(256)
void gemm_mma_kernel(const __half* __restrict__ A,
                     const __half* __restrict__ Bhi,
                     const __half* __restrict__ Blo,
                     float* __restrict__ d0, float* __restrict__ d1, float* __restrict__ d2,
                     __half* __restrict__ h0, __half* __restrict__ h1, __half* __restrict__ h2,
                     const float* __restrict__ bias0, const float* __restrict__ bias1,
                     const float* __restrict__ bias2,
                     float hs0, float hs1, float hs2)
{
    extern __shared__ char smem[];
    const uint32_t sb = smem_u32(smem);
    const int tid  = threadIdx.x;
    const int lane = tid & 31;
    const int wid  = tid >> 5;
    const int warp_m = wid >> 2;
    const int warp_n = wid & 3;
    const int bm  = blockIdx.y * BM;
    const int bnG = blockIdx.x * BN;

    float acc[4][4][4];
#pragma unroll
    for (int i = 0; i < 4; ++i)
#pragma unroll
        for (int j = 0; j < 4; ++j)
#pragma unroll
            for (int q = 0; q < 4; ++q) acc[i][j][q] = 0.f;

    const int lrow = tid >> 2;
    const int lseg = (tid & 3) * 8;
    const __half* srcA  = A   + (size_t)bm  * DD + lseg;
    const __half* srcB0 = Bhi + (size_t)bnG * DD + lseg;
    const __half* srcB1 = Blo + (size_t)bnG * DD + lseg;

    auto load_chunk = [&](int c, int s) {
        const int k0 = c * BK;
        const uint32_t dbase = sb + s * STG_BYTES;
#pragma unroll
        for (int i = 0; i < 2; ++i) {
            const int row = lrow + i * 64;
            const size_t goff = (size_t)row * DD + k0;
            const uint32_t soff = (uint32_t)(row * PADE + lseg) * 2;
            cpasync16(dbase + 0 * MAT_BYTES + soff, srcA  + goff);
            cpasync16(dbase + 1 * MAT_BYTES + soff, srcB0 + goff);
            cpasync16(dbase + 2 * MAT_BYTES + soff, srcB1 + goff);
        }
    };

    const int arow = warp_m * 64 + (lane & 7) + ((lane >> 3) & 1) * 8;
    const int acol = (lane >> 4) * 8;
    const int brow = warp_n * 32 + (lane & 7);
    const int bcol = ((lane >> 3) & 1) * 8;

    load_chunk(0, 0);
    CP_COMMIT();

    for (int c = 0; c < NCHUNKS; ++c) {
        CP_WAIT0();
        __syncthreads();
        if (c + 1 < NCHUNKS) {
            load_chunk(c + 1, (c + 1) & 1);
            CP_COMMIT();
        }
        const uint32_t st = sb + (c & 1) * STG_BYTES;

#pragma unroll
        for (int k16 = 0; k16 < BK; k16 += 16) {
            uint32_t bh[4][2], bl[4][2];
#pragma unroll
            for (int nf = 0; nf < 4; ++nf) {
                const uint32_t bo = (uint32_t)((brow + nf * 8) * PADE + bcol + k16) * 2;
                ldsm_x2(bh[nf], st + 1 * MAT_BYTES + bo);
                ldsm_x2(bl[nf], st + 2 * MAT_BYTES + bo);
            }
#pragma unroll
            for (int mf = 0; mf < 4; ++mf) {
                uint32_t ah[4];
                const uint32_t ao = (uint32_t)((arow + mf * 16) * PADE + acol + k16) * 2;
                ldsm_x4(ah, st + 0 * MAT_BYTES + ao);
#pragma unroll
                for (int nf = 0; nf < 4; ++nf) {
                    mma16816h(acc[mf][nf], ah, bh[nf]);
                    mma16816h(acc[mf][nf], ah, bl[nf]);
                }
            }
        }
    }

    const int mat = bnG >> 10;
    float* dst = (mat == 0) ? d0 : ((mat == 1) ? d1 : d2);
    __half* hdst = (mat == 0) ? h0 : ((mat == 1) ? h1 : h2);
    const float* bias = (mat == 0) ? bias0 : ((mat == 1) ? bias1 : bias2);
    const float hscale = (mat == 0) ? hs0 : ((mat == 1) ? hs1 : hs2);
    const int bn = bnG & (DD - 1);

#pragma unroll
    for (int mf = 0; mf < 4; ++mf) {
        const int row = bm + warp_m * 64 + mf * 16 + (lane >> 2);
#pragma unroll
        for (int nf = 0; nf < 4; ++nf) {
            const int col = bn + warp_n * 32 + nf * 8 + (lane & 3) * 2;
            const float b0 = bias ? bias[col] : 0.f;
            const float b1 = bias ? bias[col + 1] : 0.f;
            const float v00 = acc[mf][nf][0] + b0;
            const float v01 = acc[mf][nf][1] + b1;
            const float v10 = acc[mf][nf][2] + b0;
            const float v11 = acc[mf][nf][3] + b1;
            if (dst) {
                *(float2*)(dst + (size_t)row * DD + col) = make_float2(v00, v01);
                *(float2*)(dst + (size_t)(row + 8) * DD + col) = make_float2(v10, v11);
            }
            if (hdst) {
                __half2 q0 = __floats2half2_rn(v00 * hscale, v01 * hscale);
                __half2 q1 = __floats2half2_rn(v10 * hscale, v11 * hscale);
                *(__half2*)(hdst + (size_t)row * DD + col) = q0;
                *(__half2*)(hdst + (size_t)(row + 8) * DD + col) = q1;
            }
        }
    }
}

// ---------------------------------------------------------------------------
// Causal flash attention, fp16 mma.sync, fp16 in, fp16 out, cp.async 2-stage.
// ---------------------------------------------------------------------------
__global__ __launch_bounds__(128)
void attn_mma_kernel(const __half* __restrict__ Qh, const __half* __restrict__ Kh,
                     const __half* __restrict__ Vh, __half* __restrict__ Oh)
{
    __shared__ __half Qs[64][AT_PAD];
    __shared__ __half Ks[2][64][AT_PAD];
    __shared__ __half Vs[2][64][AT_PAD];

    const int qt  = gridDim.x - 1 - blockIdx.x;   // heavy tiles launch first
    const int bh  = blockIdx.y;
    const int b   = bh >> 4;
    const int h   = bh & 15;
    const int tid = threadIdx.x;
    const int lane = tid & 31;
    const int w   = tid >> 5;
    const int q0  = qt * 64;
    const size_t base = (size_t)b * TT * DD + (size_t)h * DHH;

    auto load_kv = [&](int jt, int s) {
        const int k0 = jt * 64;
#pragma unroll
        for (int i = 0; i < 4; ++i) {
            const int seg = tid * 4 + i;
            const int row = seg >> 3;
            const int c8  = (seg & 7) * 8;
            const size_t goff = base + (size_t)(k0 + row) * DD + c8;
            cpasync16(smem_u32(&Ks[s][row][c8]), Kh + goff);
            cpasync16(smem_u32(&Vs[s][row][c8]), Vh + goff);
        }
    };

#pragma unroll
    for (int i = 0; i < 4; ++i) {
        const int seg = tid * 4 + i;
        const int row = seg >> 3;
        const int c8  = (seg & 7) * 8;
        *(uint4*)&Qs[row][c8] = *(const uint4*)(Qh + base + (size_t)(q0 + row) * DD + c8);
    }

    load_kv(0, 0);
    CP_COMMIT();
    __syncthreads();

    uint32_t qf[4][4];
    {
        const int arow = w * 16 + (lane & 7) + ((lane >> 3) & 1) * 8;
        const int acol = (lane >> 4) * 8;
#pragma unroll
        for (int j = 0; j < 4; ++j)
            ldsm_x4(qf[j], smem_u32(&Qs[arow][acol + j * 16]));
    }

    float m0 = -1e30f, m1 = -1e30f, l0 = 0.f, l1 = 0.f;
    float oacc[8][4];
#pragma unroll
    for (int nf = 0; nf < 8; ++nf)
#pragma unroll
        for (int q = 0; q < 4; ++q) oacc[nf][q] = 0.f;

    const int brow = lane & 7;
    const int bcol = ((lane >> 3) & 1) * 8;
    const int vrow = lane & 15;

    for (int jt = 0; jt <= qt; ++jt) {
        const int s = jt & 1;
        CP_WAIT0();
        __syncthreads();
        if (jt + 1 <= qt) {
            load_kv(jt + 1, s ^ 1);
            CP_COMMIT();
        }

        float sacc[8][4];
#pragma unroll
        for (int nf = 0; nf < 8; ++nf)
#pragma unroll
            for (int q = 0; q < 4; ++q) sacc[nf][q] = 0.f;

#pragma unroll
        for (int nf = 0; nf < 8; ++nf) {
            uint32_t kb[4][2];
#pragma unroll
            for (int j = 0; j < 4; ++j)
                ldsm_x2(kb[j], smem_u32(&Ks[s][nf * 8 + brow][j * 16 + bcol]));
#pragma unroll
            for (int j = 0; j < 4; ++j)
                mma16816h(sacc[nf], qf[j], kb[j]);
        }

        if (jt == qt) {
            const int ql0 = w * 16 + (lane >> 2);
#pragma unroll
            for (int nf = 0; nf < 8; ++nf) {
                const int kl = nf * 8 + (lane & 3) * 2;
                if (kl + 0 > ql0)     sacc[nf][0] += -1e9f;
                if (kl + 1 > ql0)     sacc[nf][1] += -1e9f;
                if (kl + 0 > ql0 + 8) sacc[nf][2] += -1e9f;
                if (kl + 1 > ql0 + 8) sacc[nf][3] += -1e9f;
            }
        }

        float mn0 = m0, mn1 = m1;
#pragma unroll
        for (int nf = 0; nf < 8; ++nf) {
            mn0 = fmaxf(mn0, fmaxf(sacc[nf][0], sacc[nf][1]));
            mn1 = fmaxf(mn1, fmaxf(sacc[nf][2], sacc[nf][3]));
        }
        mn0 = fmaxf(mn0, __shfl_xor_sync(0xffffffffu, mn0, 1));
        mn0 = fmaxf(mn0, __shfl_xor_sync(0xffffffffu, mn0, 2));
        mn1 = fmaxf(mn1, __shfl_xor_sync(0xffffffffu, mn1, 1));
        mn1 = fmaxf(mn1, __shfl_xor_sync(0xffffffffu, mn1, 2));
        const float alpha0 = __expf(m0 - mn0);
        const float alpha1 = __expf(m1 - mn1);
        m0 = mn0; m1 = mn1;

        float rs0 = 0.f, rs1 = 0.f;
        uint32_t pa[4][4];
#pragma unroll
        for (int j = 0; j < 4; ++j) {
            {
                float p0 = __expf(sacc[2 * j][0] - m0);
                float p1 = __expf(sacc[2 * j][1] - m0);
                float p2 = __expf(sacc[2 * j][2] - m1);
                float p3 = __expf(sacc[2 * j][3] - m1);
                rs0 += p0 + p1; rs1 += p2 + p3;
                __half2 h01 = __floats2half2_rn(p0, p1);
                __half2 h23 = __floats2half2_rn(p2, p3);
                pa[j][0] = *(uint32_t*)&h01;
                pa[j][1] = *(uint32_t*)&h23;
            }
            {
                float p0 = __expf(sacc[2 * j + 1][0] - m0);
                float p1 = __expf(sacc[2 * j + 1][1] - m0);
                float p2 = __expf(sacc[2 * j + 1][2] - m1);
                float p3 = __expf(sacc[2 * j + 1][3] - m1);
                rs0 += p0 + p1; rs1 += p2 + p3;
                __half2 h01 = __floats2half2_rn(p0, p1);
                __half2 h23 = __floats2half2_rn(p2, p3);
                pa[j][2] = *(uint32_t*)&h01;
                pa[j][3] = *(uint32_t*)&h23;
            }
        }
        l0 = l0 * alpha0 + rs0;
        l1 = l1 * alpha1 + rs1;

#pragma unroll
        for (int nf = 0; nf < 8; ++nf) {
            oacc[nf][0] *= alpha0; oacc[nf][1] *= alpha0;
            oacc[nf][2] *= alpha1; oacc[nf][3] *= alpha1;
        }

#pragma unroll
        for (int nf = 0; nf < 8; ++nf) {
            uint32_t vb[4][2];
#pragma unroll
            for (int j = 0; j < 4; ++j)
                ldsm_x2t(vb[j], smem_u32(&Vs[s][j * 16 + vrow][nf * 8]));
#pragma unroll
            for (int j = 0; j < 4; ++j)
                mma16816h(oacc[nf], pa[j], vb[j]);
        }
        __syncthreads();
    }

    l0 += __shfl_xor_sync(0xffffffffu, l0, 1);
    l0 += __shfl_xor_sync(0xffffffffu, l0, 2);
    l1 += __shfl_xor_sync(0xffffffffu, l1, 1);
    l1 += __shfl_xor_sync(0xffffffffu, l1, 2);
    const float inv0 = 1.0f / l0;
    const float inv1 = 1.0f / l1;

    const int r0 = q0 + w * 16 + (lane >> 2);
#pragma unroll
    for (int nf = 0; nf < 8; ++nf) {
        const int col = nf * 8 + (lane & 3) * 2;
        __half2 o0 = __floats2half2_rn(oacc[nf][0] * inv0, oacc[nf][1] * inv0);
        __half2 o1 = __floats2half2_rn(oacc[nf][2] * inv1, oacc[nf][3] * inv1);
        *(__half2*)(Oh + base + (size_t)r0 * DD + col) = o0;
        *(__half2*)(Oh + base + (size_t)(r0 + 8) * DD + col) = o1;
    }
}

// ---------------------------------------------------------------------------
// Launch
// Inputs: x, k_cache, v_cache, mask, Wq, bq, Wk, Wv, bv, Wo, bo
// Output: [out | k_cache | v_cache]
// ---------------------------------------------------------------------------
extern "C" void kernel_launch(void* const* d_in, const int* in_sizes, int n_in,
                              void* d_out, int out_size)
{
    (void)in_sizes; (void)n_in;
    const float* x  = (const float*)d_in[0];
    const float* Wq = (const float*)d_in[4];
    const float* bq = (const float*)d_in[5];
    const float* Wk = (const float*)d_in[6];
    const float* Wv = (const float*)d_in[7];
    const float* bv = (const float*)d_in[8];
    const float* Wo = (const float*)d_in[9];
    const float* bo = (const float*)d_in[10];
    float* out = (float*)d_out;

    float *kfp, *vfp;
    __half *xh, *ah, *qh, *kh, *vh, *whi, *wlo;
    cudaGetSymbolAddress((void**)&kfp, g_kfall);
    cudaGetSymbolAddress((void**)&vfp, g_vfall);
    cudaGetSymbolAddress((void**)&xh,  g_xh);
    cudaGetSymbolAddress((void**)&ah,  g_ah);
    cudaGetSymbolAddress((void**)&qh,  g_qh);
    cudaGetSymbolAddress((void**)&kh,  g_kh);
    cudaGetSymbolAddress((void**)&vh,  g_vh);
    cudaGetSymbolAddress((void**)&whi, g_wt_hi);
    cudaGetSymbolAddress((void**)&wlo, g_wt_lo);

    const size_t btd = (size_t)BT * DD;
    const size_t wsz = (size_t)DD * DD;
    float* kdst = kfp;
    float* vdst = vfp;
    if ((size_t)out_size >= 3 * btd) {
        kdst = out + btd;
        vdst = out + 2 * btd;
    }

    // 1. weight transposes + fp16 hi/lo splits (one launch)
    wconv4_kernel<<<dim3(32, 32, 4), 256>>>(Wq, Wk, Wv, Wo, whi, wlo);

    // 2. x -> fp16
    tohalf_kernel<<<(int)(btd / 1024), 256>>>(x, xh);

    // 3. fused QKV projection (N = 3072):
    //    mat0: q -> fp16(scaled) only; mat1: k -> fp32 + fp16(scaled); mat2: v -> fp32 + fp16
    cudaFuncSetAttribute(gemm_mma_kernel, cudaFuncAttributeMaxDynamicSharedMemorySize, GEMM_SMEM);
    gemm_mma_kernel<<<dim3(3 * DD / BN, BT / BM), 256, GEMM_SMEM>>>(
        xh, whi, wlo,
        nullptr, kdst, vdst,
        qh, kh, vh,
        bq, nullptr, bv,
        QK_SCALE, QK_SCALE, 1.0f);

    // 4. attention (fp16 in/out)
    attn_mma_kernel<<<dim3(TT / 64, BB * HH), 128>>>(qh, kh, vh, ah);

    // 5. output projection (fp32 out)
    gemm_mma_kernel<<<dim3(DD / BN, BT / BM), 256, GEMM_SMEM>>>(
        ah, whi + 3 * wsz, wlo + 3 * wsz,
        out, out, out,
        nullptr, nullptr, nullptr,
        bo, bo, bo,
        1.0f, 1.0f, 1.0f);
}

// round 7
// speedup vs baseline: 4.9788x; 1.3839x over previous
#include <cuda_runtime.h>
#include <cuda_fp16.h>
#include <cstdint>
#include <cstddef>

// Problem constants
#define BB   8
#define TT   448
#define DD   1024
#define HH   16
#define DHH  64
#define BT   (BB * TT)              // 3584
#define QK_SCALE 0.35355339059327373f   // 64^(-0.25)

// GEMM tiling (mma.sync path)
#define BM 128
#define BN 128
#define BK 32
#define NCHUNKS (DD / BK)           // 32
#define PADE 40                     // padded row stride in halves
#define MAT_BYTES (128 * PADE * 2)  // 10240 per matrix tile
#define STG_BYTES (2 * MAT_BYTES)   // 20480 per stage (A, B)
#define GEMM_SMEM (2 * STG_BYTES)   // 40960

#define AT_PAD 72                   // attn smem row stride (halves)

// Scratch (allocation-free rule: __device__ globals)
__device__ float  g_kfall[(size_t)BT * DD];
__device__ float  g_vfall[(size_t)BT * DD];
__device__ __half g_xh[(size_t)BT * DD];        // x, fp16
__device__ __half g_ah[(size_t)BT * DD];        // attn out, fp16
__device__ __half g_qh[(size_t)BT * DD];        // q * QK_SCALE, fp16
__device__ __half g_kh[(size_t)BT * DD];        // k * QK_SCALE, fp16
__device__ __half g_vh[(size_t)BT * DD];        // v, fp16
__device__ __half g_wt[4][(size_t)DD * DD];     // W^T, [n][k], fp16

// ---------------------------------------------------------------------------
// PTX helpers (plain sm_80+ ISA)
// ---------------------------------------------------------------------------
__device__ __forceinline__ uint32_t smem_u32(const void* p) {
    uint32_t a;
    asm("{ .reg .u64 t; cvta.to.shared.u64 t, %1; cvt.u32.u64 %0, t; }" : "=r"(a) : "l"(p));
    return a;
}
__device__ __forceinline__ void cpasync16(uint32_t dst, const void* src) {
    asm volatile("cp.async.cg.shared.global [%0], [%1], 16;" :: "r"(dst), "l"(src));
}
#define CP_COMMIT() asm volatile("cp.async.commit_group;" ::: "memory")
#define CP_WAIT0()  asm volatile("cp.async.wait_group 0;" ::: "memory")

__device__ __forceinline__ void ldsm_x4(uint32_t* r, uint32_t a) {
    asm volatile("ldmatrix.sync.aligned.m8n8.x4.shared.b16 {%0,%1,%2,%3}, [%4];"
        : "=r"(r[0]), "=r"(r[1]), "=r"(r[2]), "=r"(r[3]) : "r"(a));
}
__device__ __forceinline__ void ldsm_x2(uint32_t* r, uint32_t a) {
    asm volatile("ldmatrix.sync.aligned.m8n8.x2.shared.b16 {%0,%1}, [%2];"
        : "=r"(r[0]), "=r"(r[1]) : "r"(a));
}
__device__ __forceinline__ void ldsm_x2t(uint32_t* r, uint32_t a) {
    asm volatile("ldmatrix.sync.aligned.m8n8.x2.trans.shared.b16 {%0,%1}, [%2];"
        : "=r"(r[0]), "=r"(r[1]) : "r"(a));
}
__device__ __forceinline__ void mma16816h(float* d, const uint32_t* a, uint32_t b0, uint32_t b1) {
    asm volatile("mma.sync.aligned.m16n8k16.row.col.f32.f16.f16.f32 "
        "{%0,%1,%2,%3}, {%4,%5,%6,%7}, {%8,%9}, {%0,%1,%2,%3};"
        : "+f"(d[0]), "+f"(d[1]), "+f"(d[2]), "+f"(d[3])
        : "r"(a[0]), "r"(a[1]), "r"(a[2]), "r"(a[3]), "r"(b0), "r"(b1));
}

// ---------------------------------------------------------------------------
// fp32 -> fp16 convert (elementwise), 4 floats/thread
// ---------------------------------------------------------------------------
__global__ __launch_bounds__(256)
void tohalf_kernel(const float* __restrict__ in, __half* __restrict__ outp)
{
    const size_t i = ((size_t)blockIdx.x * 256 + threadIdx.x) * 4;
    float4 v = *(const float4*)(in + i);
    __half2 a = __floats2half2_rn(v.x, v.y);
    __half2 b = __floats2half2_rn(v.z, v.w);
    uint2 p;
    p.x = *(uint32_t*)&a; p.y = *(uint32_t*)&b;
    *(uint2*)(outp + i) = p;
}

// ---------------------------------------------------------------------------
// Weight transpose + fp16 convert, all 4 matrices in one launch (z dim)
// ---------------------------------------------------------------------------
__global__ __launch_bounds__(256)
void wconv4_kernel(const float* __restrict__ W0, const float* __restrict__ W1,
                   const float* __restrict__ W2, const float* __restrict__ W3,
                   __half* __restrict__ wtB)
{
    __shared__ float t[32][33];
    const int z = blockIdx.z;
    const float* W = (z == 0) ? W0 : (z == 1) ? W1 : (z == 2) ? W2 : W3;
    __half* wt = wtB + (size_t)z * DD * DD;
    const int k0 = blockIdx.y * 32, n0 = blockIdx.x * 32;
    const int tx = threadIdx.x & 31, ty = threadIdx.x >> 5;
#pragma unroll
    for (int i = 0; i < 4; ++i)
        t[ty + i * 8][tx] = W[(size_t)(k0 + ty + i * 8) * DD + n0 + tx];
    __syncthreads();
#pragma unroll
    for (int i = 0; i < 4; ++i) {
        const int n = n0 + ty + i * 8, k = k0 + tx;
        wt[(size_t)n * DD + k] = __float2half(t[tx][ty + i * 8]);
    }
}

// ---------------------------------------------------------------------------
// Single-fp16 GEMM via mma.sync:  C = A(fp16) @ W^T(fp16) (+bias), fp32 accum.
// Epilogue emits fp32 (+bias) and/or fp16 (*hscale) copies.
// CTA 128x128, BK=32, 256 threads (8 warps 2x4), cp.async double buffer.
// B operand fetched with ldmatrix.x4 (2 instrs per k16 per warp).
// ---------------------------------------------------------------------------
__global__ __launch_bounds__(256)
void gemm_mma_kernel(const __half* __restrict__ A,
                     const __half* __restrict__ B,
                     float* __restrict__ d0, float* __restrict__ d1, float* __restrict__ d2,
                     __half* __restrict__ h0, __half* __restrict__ h1, __half* __restrict__ h2,
                     const float* __restrict__ bias0, const float* __restrict__ bias1,
                     const float* __restrict__ bias2,
                     float hs0, float hs1, float hs2)
{
    extern __shared__ char smem[];
    const uint32_t sb = smem_u32(smem);
    const int tid  = threadIdx.x;
    const int lane = tid & 31;
    const int wid  = tid >> 5;
    const int warp_m = wid >> 2;
    const int warp_n = wid & 3;
    const int bm  = blockIdx.y * BM;
    const int bnG = blockIdx.x * BN;

    float acc[4][4][4];
#pragma unroll
    for (int i = 0; i < 4; ++i)
#pragma unroll
        for (int j = 0; j < 4; ++j)
#pragma unroll
            for (int q = 0; q < 4; ++q) acc[i][j][q] = 0.f;

    const int lrow = tid >> 2;
    const int lseg = (tid & 3) * 8;
    const __half* srcA = A + (size_t)bm  * DD + lseg;
    const __half* srcB = B + (size_t)bnG * DD + lseg;

    auto load_chunk = [&](int c, int s) {
        const int k0 = c * BK;
        const uint32_t dbase = sb + s * STG_BYTES;
#pragma unroll
        for (int i = 0; i < 2; ++i) {
            const int row = lrow + i * 64;
            const size_t goff = (size_t)row * DD + k0;
            const uint32_t soff = (uint32_t)(row * PADE + lseg) * 2;
            cpasync16(dbase + 0 * MAT_BYTES + soff, srcA + goff);
            cpasync16(dbase + 1 * MAT_BYTES + soff, srcB + goff);
        }
    };

    // x4 ldmatrix addressing (same pattern for A and B):
    // row = base + (lane&7) + ((lane>>3)&1)*8 ; col = k16 + (lane>>4)*8
    const int xrow = (lane & 7) + ((lane >> 3) & 1) * 8;
    const int xcol = (lane >> 4) * 8;
    const int arow = warp_m * 64 + xrow;
    const int brow = warp_n * 32 + xrow;

    load_chunk(0, 0);
    CP_COMMIT();

    for (int c = 0; c < NCHUNKS; ++c) {
        CP_WAIT0();
        __syncthreads();
        if (c + 1 < NCHUNKS) {
            load_chunk(c + 1, (c + 1) & 1);
            CP_COMMIT();
        }
        const uint32_t st = sb + (c & 1) * STG_BYTES;

#pragma unroll
        for (int k16 = 0; k16 < BK; k16 += 16) {
            // B frags: 2 x ldsm_x4, each covers 16 n-rows x 16 k
            // regs: [0]=n0:8/k0:8, [1]=n8:16/k0:8, [2]=n0:8/k8:16, [3]=n8:16/k8:16
            uint32_t bb[2][4];
#pragma unroll
            for (int nf2 = 0; nf2 < 2; ++nf2) {
                const uint32_t bo = (uint32_t)((brow + nf2 * 16) * PADE + xcol + k16) * 2;
                ldsm_x4(bb[nf2], st + 1 * MAT_BYTES + bo);
            }
#pragma unroll
            for (int mf = 0; mf < 4; ++mf) {
                uint32_t ah[4];
                const uint32_t ao = (uint32_t)((arow + mf * 16) * PADE + xcol + k16) * 2;
                ldsm_x4(ah, st + 0 * MAT_BYTES + ao);
#pragma unroll
                for (int nf2 = 0; nf2 < 2; ++nf2) {
                    mma16816h(acc[mf][nf2 * 2 + 0], ah, bb[nf2][0], bb[nf2][2]);
                    mma16816h(acc[mf][nf2 * 2 + 1], ah, bb[nf2][1], bb[nf2][3]);
                }
            }
        }
    }

    const int mat = bnG >> 10;
    float* dst = (mat == 0) ? d0 : ((mat == 1) ? d1 : d2);
    __half* hdst = (mat == 0) ? h0 : ((mat == 1) ? h1 : h2);
    const float* bias = (mat == 0) ? bias0 : ((mat == 1) ? bias1 : bias2);
    const float hscale = (mat == 0) ? hs0 : ((mat == 1) ? hs1 : hs2);
    const int bn = bnG & (DD - 1);

#pragma unroll
    for (int mf = 0; mf < 4; ++mf) {
        const int row = bm + warp_m * 64 + mf * 16 + (lane >> 2);
#pragma unroll
        for (int nf = 0; nf < 4; ++nf) {
            const int col = bn + warp_n * 32 + nf * 8 + (lane & 3) * 2;
            const float b0 = bias ? bias[col] : 0.f;
            const float b1 = bias ? bias[col + 1] : 0.f;
            const float v00 = acc[mf][nf][0] + b0;
            const float v01 = acc[mf][nf][1] + b1;
            const float v10 = acc[mf][nf][2] + b0;
            const float v11 = acc[mf][nf][3] + b1;
            if (dst) {
                *(float2*)(dst + (size_t)row * DD + col) = make_float2(v00, v01);
                *(float2*)(dst + (size_t)(row + 8) * DD + col) = make_float2(v10, v11);
            }
            if (hdst) {
                __half2 q0 = __floats2half2_rn(v00 * hscale, v01 * hscale);
                __half2 q1 = __floats2half2_rn(v10 * hscale, v11 * hscale);
                *(__half2*)(hdst + (size_t)row * DD + col) = q0;
                *(__half2*)(hdst + (size_t)(row + 8) * DD + col) = q1;
            }
        }
    }
}

// ---------------------------------------------------------------------------
// Causal flash attention, fp16 mma.sync, fp16 in/out, cp.async 2-stage.
// (unchanged from R6; 38.7us)
// ---------------------------------------------------------------------------
__global__ __launch_bounds__(128)
void attn_mma_kernel(const __half* __restrict__ Qh, const __half* __restrict__ Kh,
                     const __half* __restrict__ Vh, __half* __restrict__ Oh)
{
    __shared__ __half Qs[64][AT_PAD];
    __shared__ __half Ks[2][64][AT_PAD];
    __shared__ __half Vs[2][64][AT_PAD];

    const int qt  = gridDim.x - 1 - blockIdx.x;
    const int bh  = blockIdx.y;
    const int b   = bh >> 4;
    const int h   = bh & 15;
    const int tid = threadIdx.x;
    const int lane = tid & 31;
    const int w   = tid >> 5;
    const int q0  = qt * 64;
    const size_t base = (size_t)b * TT * DD + (size_t)h * DHH;

    auto load_kv = [&](int jt, int s) {
        const int k0 = jt * 64;
#pragma unroll
        for (int i = 0; i < 4; ++i) {
            const int seg = tid * 4 + i;
            const int row = seg >> 3;
            const int c8  = (seg & 7) * 8;
            const size_t goff = base + (size_t)(k0 + row) * DD + c8;
            cpasync16(smem_u32(&Ks[s][row][c8]), Kh + goff);
            cpasync16(smem_u32(&Vs[s][row][c8]), Vh + goff);
        }
    };

#pragma unroll
    for (int i = 0; i < 4; ++i) {
        const int seg = tid * 4 + i;
        const int row = seg >> 3;
        const int c8  = (seg & 7) * 8;
        *(uint4*)&Qs[row][c8] = *(const uint4*)(Qh + base + (size_t)(q0 + row) * DD + c8);
    }

    load_kv(0, 0);
    CP_COMMIT();
    __syncthreads();

    uint32_t qf[4][4];
    {
        const int arow = w * 16 + (lane & 7) + ((lane >> 3) & 1) * 8;
        const int acol = (lane >> 4) * 8;
#pragma unroll
        for (int j = 0; j < 4; ++j)
            ldsm_x4(qf[j], smem_u32(&Qs[arow][acol + j * 16]));
    }

    float m0 = -1e30f, m1 = -1e30f, l0 = 0.f, l1 = 0.f;
    float oacc[8][4];
#pragma unroll
    for (int nf = 0; nf < 8; ++nf)
#pragma unroll
        for (int q = 0; q < 4; ++q) oacc[nf][q] = 0.f;

    const int brow = lane & 7;
    const int bcol = ((lane >> 3) & 1) * 8;
    const int vrow = lane & 15;

    for (int jt = 0; jt <= qt; ++jt) {
        const int s = jt & 1;
        CP_WAIT0();
        __syncthreads();
        if (jt + 1 <= qt) {
            load_kv(jt + 1, s ^ 1);
            CP_COMMIT();
        }

        float sacc[8][4];
#pragma unroll
        for (int nf = 0; nf < 8; ++nf)
#pragma unroll
            for (int q = 0; q < 4; ++q) sacc[nf][q] = 0.f;

#pragma unroll
        for (int nf = 0; nf < 8; ++nf) {
            uint32_t kb[4][2];
#pragma unroll
            for (int j = 0; j < 4; ++j)
                ldsm_x2(kb[j], smem_u32(&Ks[s][nf * 8 + brow][j * 16 + bcol]));
#pragma unroll
            for (int j = 0; j < 4; ++j)
                mma16816h(sacc[nf], qf[j], kb[j][0], kb[j][1]);
        }

        if (jt == qt) {
            const int ql0 = w * 16 + (lane >> 2);
#pragma unroll
            for (int nf = 0; nf < 8; ++nf) {
                const int kl = nf * 8 + (lane & 3) * 2;
                if (kl + 0 > ql0)     sacc[nf][0] += -1e9f;
                if (kl + 1 > ql0)     sacc[nf][1] += -1e9f;
                if (kl + 0 > ql0 + 8) sacc[nf][2] += -1e9f;
                if (kl + 1 > ql0 + 8) sacc[nf][3] += -1e9f;
            }
        }

        float mn0 = m0, mn1 = m1;
#pragma unroll
        for (int nf = 0; nf < 8; ++nf) {
            mn0 = fmaxf(mn0, fmaxf(sacc[nf][0], sacc[nf][1]));
            mn1 = fmaxf(mn1, fmaxf(sacc[nf][2], sacc[nf][3]));
        }
        mn0 = fmaxf(mn0, __shfl_xor_sync(0xffffffffu, mn0, 1));
        mn0 = fmaxf(mn0, __shfl_xor_sync(0xffffffffu, mn0, 2));
        mn1 = fmaxf(mn1, __shfl_xor_sync(0xffffffffu, mn1, 1));
        mn1 = fmaxf(mn1, __shfl_xor_sync(0xffffffffu, mn1, 2));
        const float alpha0 = __expf(m0 - mn0);
        const float alpha1 = __expf(m1 - mn1);
        m0 = mn0; m1 = mn1;

        float rs0 = 0.f, rs1 = 0.f;
        uint32_t pa[4][4];
#pragma unroll
        for (int j = 0; j < 4; ++j) {
            {
                float p0 = __expf(sacc[2 * j][0] - m0);
                float p1 = __expf(sacc[2 * j][1] - m0);
                float p2 = __expf(sacc[2 * j][2] - m1);
                float p3 = __expf(sacc[2 * j][3] - m1);
                rs0 += p0 + p1; rs1 += p2 + p3;
                __half2 h01 = __floats2half2_rn(p0, p1);
                __half2 h23 = __floats2half2_rn(p2, p3);
                pa[j][0] = *(uint32_t*)&h01;
                pa[j][1] = *(uint32_t*)&h23;
            }
            {
                float p0 = __expf(sacc[2 * j + 1][0] - m0);
                float p1 = __expf(sacc[2 * j + 1][1] - m0);
                float p2 = __expf(sacc[2 * j + 1][2] - m1);
                float p3 = __expf(sacc[2 * j + 1][3] - m1);
                rs0 += p0 + p1; rs1 += p2 + p3;
                __half2 h01 = __floats2half2_rn(p0, p1);
                __half2 h23 = __floats2half2_rn(p2, p3);
                pa[j][2] = *(uint32_t*)&h01;
                pa[j][3] = *(uint32_t*)&h23;
            }
        }
        l0 = l0 * alpha0 + rs0;
        l1 = l1 * alpha1 + rs1;

#pragma unroll
        for (int nf = 0; nf < 8; ++nf) {
            oacc[nf][0] *= alpha0; oacc[nf][1] *= alpha0;
            oacc[nf][2] *= alpha1; oacc[nf][3] *= alpha1;
        }

#pragma unroll
        for (int nf = 0; nf < 8; ++nf) {
            uint32_t vb[4][2];
#pragma unroll
            for (int j = 0; j < 4; ++j)
                ldsm_x2t(vb[j], smem_u32(&Vs[s][j * 16 + vrow][nf * 8]));
#pragma unroll
            for (int j = 0; j < 4; ++j)
                mma16816h(oacc[nf], pa[j], vb[j][0], vb[j][1]);
        }
        __syncthreads();
    }

    l0 += __shfl_xor_sync(0xffffffffu, l0, 1);
    l0 += __shfl_xor_sync(0xffffffffu, l0, 2);
    l1 += __shfl_xor_sync(0xffffffffu, l1, 1);
    l1 += __shfl_xor_sync(0xffffffffu, l1, 2);
    const float inv0 = 1.0f / l0;
    const float inv1 = 1.0f / l1;

    const int r0 = q0 + w * 16 + (lane >> 2);
#pragma unroll
    for (int nf = 0; nf < 8; ++nf) {
        const int col = nf * 8 + (lane & 3) * 2;
        __half2 o0 = __floats2half2_rn(oacc[nf][0] * inv0, oacc[nf][1] * inv0);
        __half2 o1 = __floats2half2_rn(oacc[nf][2] * inv1, oacc[nf][3] * inv1);
        *(__half2*)(Oh + base + (size_t)r0 * DD + col) = o0;
        *(__half2*)(Oh + base + (size_t)(r0 + 8) * DD + col) = o1;
    }
}

// ---------------------------------------------------------------------------
// Launch
// Inputs: x, k_cache, v_cache, mask, Wq, bq, Wk, Wv, bv, Wo, bo
// Output: [out | k_cache | v_cache]
// ---------------------------------------------------------------------------
extern "C" void kernel_launch(void* const* d_in, const int* in_sizes, int n_in,
                              void* d_out, int out_size)
{
    (void)in_sizes; (void)n_in;
    const float* x  = (const float*)d_in[0];
    const float* Wq = (const float*)d_in[4];
    const float* bq = (const float*)d_in[5];
    const float* Wk = (const float*)d_in[6];
    const float* Wv = (const float*)d_in[7];
    const float* bv = (const float*)d_in[8];
    const float* Wo = (const float*)d_in[9];
    const float* bo = (const float*)d_in[10];
    float* out = (float*)d_out;

    float *kfp, *vfp;
    __half *xh, *ah, *qh, *kh, *vh, *wt;
    cudaGetSymbolAddress((void**)&kfp, g_kfall);
    cudaGetSymbolAddress((void**)&vfp, g_vfall);
    cudaGetSymbolAddress((void**)&xh,  g_xh);
    cudaGetSymbolAddress((void**)&ah,  g_ah);
    cudaGetSymbolAddress((void**)&qh,  g_qh);
    cudaGetSymbolAddress((void**)&kh,  g_kh);
    cudaGetSymbolAddress((void**)&vh,  g_vh);
    cudaGetSymbolAddress((void**)&wt,  g_wt);

    const size_t btd = (size_t)BT * DD;
    const size_t wsz = (size_t)DD * DD;
    float* kdst = kfp;
    float* vdst = vfp;
    if ((size_t)out_size >= 3 * btd) {
        kdst = out + btd;
        vdst = out + 2 * btd;
    }

    // 1. weight transposes + fp16 convert (one launch)
    wconv4_kernel<<<dim3(32, 32, 4), 256>>>(Wq, Wk, Wv, Wo, wt);

    // 2. x -> fp16
    tohalf_kernel<<<(int)(btd / 1024), 256>>>(x, xh);

    // 3. fused QKV projection (N = 3072)
    cudaFuncSetAttribute(gemm_mma_kernel, cudaFuncAttributeMaxDynamicSharedMemorySize, GEMM_SMEM);
    gemm_mma_kernel<<<dim3(3 * DD / BN, BT / BM), 256, GEMM_SMEM>>>(
        xh, wt,
        nullptr, kdst, vdst,
        qh, kh, vh,
        bq, nullptr, bv,
        QK_SCALE, QK_SCALE, 1.0f);

    // 4. attention (fp16 in/out)
    attn_mma_kernel<<<dim3(TT / 64, BB * HH), 128>>>(qh, kh, vh, ah);

    // 5. output projection (fp32 out)
    gemm_mma_kernel<<<dim3(DD / BN, BT / BM), 256, GEMM_SMEM>>>(
        ah, wt + 3 * wsz,
        out, out, out,
        nullptr, nullptr, nullptr,
        bo, bo, bo,
        1.0f, 1.0f, 1.0f);
}